// round 3
// baseline (speedup 1.0000x reference)
#include <cuda_runtime.h>
#include <cstdint>
#include <math.h>

#define DI __device__ __forceinline__

// ----------------------------------------------------------------------------
// Device scratch (no cudaMalloc allowed)
// ----------------------------------------------------------------------------
__device__ float g_fused[8ull * 4096ull * 1024ull];  // [b][hw2][1024 ch], tf32-rounded
__device__ float g_weff [8ull * 512ull  * 1024ull];  // [b][o][c],         tf32-rounded
__device__ float g_scale[8 * 1024];                  // per-(b,ch) gate (1.0 for LL)
__device__ float g_sum  [8 * 768];                   // hf channel sums
__device__ float g_bns  [512];                       // folded BN scale
__device__ float g_bnb  [512];                       // folded BN bias

// ----------------------------------------------------------------------------
// Helpers (baseline PTX only — no tcgen05/TMA, target is compute_103 non-'a')
// ----------------------------------------------------------------------------
DI uint32_t smem_u32(const void* p) {
    uint32_t a;
    asm("{ .reg .u64 t; cvta.to.shared.u64 t, %1; cvt.u32.u64 %0, t; }" : "=r"(a) : "l"(p));
    return a;
}
DI float tf32r(float x) {
    uint32_t u;
    asm("cvt.rna.tf32.f32 %0, %1;" : "=r"(u) : "f"(x));
    return __uint_as_float(u);
}
DI uint32_t sw128(uint32_t o) { return o ^ ((o >> 3) & 0x70u); }

DI void cpasync16(uint32_t dst, const float* src) {
    asm volatile("cp.async.cg.shared.global [%0], [%1], 16;"
                 :: "r"(dst), "l"(__cvta_generic_to_global(src)) : "memory");
}
DI void cp_commit() { asm volatile("cp.async.commit_group;" ::: "memory"); }
template <int N> DI void cp_wait() { asm volatile("cp.async.wait_group %0;" :: "n"(N) : "memory"); }

// tf32 HMMA: D[16x8] += A[16x8] * B[8x8]
DI void mma8(float* c, const uint32_t* a, const uint32_t* b) {
    asm volatile(
        "mma.sync.aligned.m16n8k8.row.col.f32.tf32.tf32.f32 "
        "{%0,%1,%2,%3}, {%4,%5,%6,%7}, {%8,%9}, {%0,%1,%2,%3};"
        : "+f"(c[0]), "+f"(c[1]), "+f"(c[2]), "+f"(c[3])
        : "r"(a[0]), "r"(a[1]), "r"(a[2]), "r"(a[3]), "r"(b[0]), "r"(b[1]));
}

// ----------------------------------------------------------------------------
// K0: zero the hf channel-sum accumulator
// ----------------------------------------------------------------------------
__global__ void k_zero() {
    int i = blockIdx.x * 256 + threadIdx.x;
    if (i < 8 * 768) g_sum[i] = 0.0f;
}

// ----------------------------------------------------------------------------
// K1: Haar DWT -> g_fused [b][hw2][1024] + hf channel sums
// grid (128 pos-tiles, 8 c-tiles, 8 b), 256 threads
// ----------------------------------------------------------------------------
__global__ __launch_bounds__(256) void k_wavelet(const float* __restrict__ x) {
    const int b = blockIdx.z, c0 = blockIdx.y * 32, p0 = blockIdx.x * 32;
    const int tid = threadIdx.x, lane = tid & 31, w = tid >> 5;

    __shared__ float sLL[32][33];
    __shared__ float sHF[3][32][33];

#pragma unroll
    for (int it = 0; it < 4; ++it) {
        int cc = it * 8 + w;
        int c = c0 + cc;
        int hw2 = p0 + lane;
        int h2 = hw2 >> 6, w2 = hw2 & 63;
        const float* xr = x + (((size_t)(b * 256 + c) * 128 + 2 * h2) * 128 + 2 * w2);
        float2 t0 = *reinterpret_cast<const float2*>(xr);
        float2 t1 = *reinterpret_cast<const float2*>(xr + 128);
        float ll = 0.5f * (t0.x + t0.y + t1.x + t1.y);
        float lh = 0.5f * (t0.x + t0.y - t1.x - t1.y);
        float hl = 0.5f * (t0.x - t0.y + t1.x - t1.y);
        float hh = 0.5f * (t0.x - t0.y - t1.x + t1.y);
        sLL[cc][lane] = ll;
        sHF[0][cc][lane] = lh;
        sHF[1][cc][lane] = hl;
        sHF[2][cc][lane] = hh;
        float slh = lh, shl = hl, shh = hh;
#pragma unroll
        for (int off = 16; off; off >>= 1) {
            slh += __shfl_down_sync(0xffffffffu, slh, off);
            shl += __shfl_down_sync(0xffffffffu, shl, off);
            shh += __shfl_down_sync(0xffffffffu, shh, off);
        }
        if (lane == 0) {
            atomicAdd(&g_sum[b * 768 + 3 * c + 0], slh);
            atomicAdd(&g_sum[b * 768 + 3 * c + 1], shl);
            atomicAdd(&g_sum[b * 768 + 3 * c + 2], shh);
        }
    }
    __syncthreads();

    // Transposed, coalesced write into [hw][channel] layout (tf32-pre-rounded)
#pragma unroll
    for (int it = 0; it < 16; ++it) {
        int wdx = it * 256 + tid;
        int pp = wdx >> 7, cl = wdx & 127;
        float v;
        int col;
        if (cl < 32) {
            v = sLL[cl][pp];
            col = c0 + cl;
        } else {
            int k = cl - 32;
            int cc = k / 3;
            int sb = k - 3 * cc;
            v = sHF[sb][cc][pp];
            col = 256 + 3 * c0 + k;
        }
        g_fused[((size_t)(b * 4096 + p0 + pp) << 10) + col] = tf32r(v);
    }
}

// ----------------------------------------------------------------------------
// K2: blocks 0..7 = per-batch MLP gate; block 8 = folded BN params
// ----------------------------------------------------------------------------
__global__ __launch_bounds__(256) void k_mlp(const float* __restrict__ w1, const float* __restrict__ w2,
                                             const float* __restrict__ gamma, const float* __restrict__ beta,
                                             const float* __restrict__ mean, const float* __restrict__ var) {
    int tid = threadIdx.x;
    if (blockIdx.x == 8) {
        for (int o = tid; o < 512; o += 256) {
            float s = gamma[o] * rsqrtf(var[o] + 1e-5f);
            g_bns[o] = s;
            g_bnb[o] = beta[o] - mean[o] * s;
        }
        return;
    }
    int b = blockIdx.x;
    __shared__ float s_mean[768];
    __shared__ float s_y1[48];
    for (int c = tid; c < 768; c += 256) s_mean[c] = g_sum[b * 768 + c] * (1.0f / 4096.0f);
    __syncthreads();
    int w = tid >> 5, lane = tid & 31;
#pragma unroll 1
    for (int i = 0; i < 6; i++) {
        int m = w + 8 * i;
        float acc = 0.f;
        for (int j = 0; j < 24; j++) {
            int c = lane + 32 * j;
            acc += s_mean[c] * w1[m * 768 + c];
        }
#pragma unroll
        for (int off = 16; off; off >>= 1) acc += __shfl_down_sync(0xffffffffu, acc, off);
        if (lane == 0) s_y1[m] = fmaxf(acc, 0.f);
    }
    __syncthreads();
    g_scale[b * 1024 + tid] = 1.0f;  // LL channels unscaled
    for (int c = tid; c < 768; c += 256) {
        float acc = 0.f;
#pragma unroll
        for (int m = 0; m < 48; m++) acc += s_y1[m] * w2[c * 48 + m];
        g_scale[b * 1024 + 256 + c] = 1.0f / (1.0f + expf(-acc));
    }
}

// ----------------------------------------------------------------------------
// K3: W_eff[b][o][c] = conv_w[o][c] * scale[b][c], tf32-rounded
// ----------------------------------------------------------------------------
__global__ __launch_bounds__(256) void k_weff(const float* __restrict__ conv_w) {
    int idx = blockIdx.x * 256 + threadIdx.x;  // < 8*512*1024 = 2^22
    int b = idx >> 19;
    int oc = idx & 524287;
    int c = idx & 1023;
    g_weff[idx] = tf32r(conv_w[oc] * g_scale[b * 1024 + c]);
}

// ----------------------------------------------------------------------------
// K4: tf32 mma.sync GEMM. CTA tile 128M x 128N x 32K, 4-stage cp.async,
//     SW128 smem (conflict-free fragment LDS), smem-transposed epilogue with
//     fused BN+SiLU. grid (4 ntile, 32 mtile, 8 b), 256 thr (8 warps, 2x4).
// ----------------------------------------------------------------------------
static constexpr int STAGE_SZ = 32768;                 // A 16KB + B 16KB
static constexpr int SMEM_SZ  = 4 * STAGE_SZ;          // 131072

__global__ __launch_bounds__(256) void k_gemm(float* __restrict__ out) {
    extern __shared__ __align__(1024) char smem[];
    const uint32_t sb = smem_u32(smem);
    const int tid = threadIdx.x, lane = tid & 31, wid = tid >> 5;
    const int wm = wid & 1, wn = wid >> 1;           // warp grid 2(m) x 4(n)
    const int rq = lane >> 2, qq = lane & 3;
    const int b = blockIdx.z, m0 = blockIdx.y * 128, n0 = blockIdx.x * 128;

    const float* Ab = g_fused + (((size_t)(b * 4096 + m0)) << 10);
    const float* Bb = g_weff  + (((size_t)(b * 512  + n0)) << 10);

    auto produce = [&](int step) {
        int s = step & 3;
        int kc = step * 32;
        uint32_t da = sb + s * STAGE_SZ;
        uint32_t db = da + 16384;
#pragma unroll
        for (int j = 0; j < 4; j++) {
            uint32_t q = tid + 256 * j;                    // 1024 16B-chunks per 16KB tile
            uint32_t so = sw128(q * 16);
            size_t go = ((size_t)(q >> 3) << 10) + kc + ((q & 7) << 2);
            cpasync16(da + so, Ab + go);
            cpasync16(db + so, Bb + go);
        }
        cp_commit();
    };

    produce(0); produce(1); produce(2);

    float acc[4][4][4];
#pragma unroll
    for (int i = 0; i < 4; i++)
#pragma unroll
        for (int j = 0; j < 4; j++)
#pragma unroll
            for (int r = 0; r < 4; r++) acc[i][j][r] = 0.f;

    // per-thread float-index bases into the 128x32f tiles (row stride 32 floats)
    const int arow = ((wm * 64 + rq) << 5) + qq;
    const int brow = ((wn * 32 + rq) << 5) + qq;

#pragma unroll 1
    for (int kt = 0; kt < 32; ++kt) {
        cp_wait<2>();
        __syncthreads();
        if (kt < 29) produce(kt + 3);

        int s = kt & 3;
        const float* sA = reinterpret_cast<const float*>(smem + s * STAGE_SZ);
        const float* sBt = reinterpret_cast<const float*>(smem + s * STAGE_SZ + 16384);

#pragma unroll
        for (int ks = 0; ks < 4; ++ks) {
            // SW128: chunk index (k>>2) XORs with (row&7)==rq
            const int x0 = ((2 * ks) ^ rq) << 2;
            const int x1 = ((2 * ks + 1) ^ rq) << 2;
            uint32_t a[4][4], bf[4][2];
#pragma unroll
            for (int i = 0; i < 4; i++) {
                int base = arow + (i << 9);               // i*16 rows * 32 floats
                a[i][0] = __float_as_uint(sA[base + x0]);
                a[i][1] = __float_as_uint(sA[base + 256 + x0]);  // +8 rows
                a[i][2] = __float_as_uint(sA[base + x1]);
                a[i][3] = __float_as_uint(sA[base + 256 + x1]);
            }
#pragma unroll
            for (int j = 0; j < 4; j++) {
                int base = brow + (j << 8);               // j*8 rows * 32 floats
                bf[j][0] = __float_as_uint(sBt[base + x0]);
                bf[j][1] = __float_as_uint(sBt[base + x1]);
            }
#pragma unroll
            for (int i = 0; i < 4; i++)
#pragma unroll
                for (int j = 0; j < 4; j++) mma8(acc[i][j], a[i], bf[j]);
        }
    }

    // ---- epilogue: transpose through smem, fused BN + SiLU, coalesced STG ----
    __syncthreads();
    float* eP = reinterpret_cast<float*>(smem);           // [n][m], stride 132 floats
#pragma unroll
    for (int i = 0; i < 4; i++) {
        int m = wm * 64 + i * 16 + rq;
#pragma unroll
        for (int j = 0; j < 4; j++) {
            int n = wn * 32 + j * 8 + 2 * qq;
            eP[n * 132 + m]             = acc[i][j][0];
            eP[(n + 1) * 132 + m]       = acc[i][j][1];
            eP[n * 132 + m + 8]         = acc[i][j][2];
            eP[(n + 1) * 132 + m + 8]   = acc[i][j][3];
        }
    }
    __syncthreads();

#pragma unroll 1
    for (int idx = tid; idx < 128 * 32; idx += 256) {
        int row = idx >> 5;            // local output channel (uniform per warp)
        int seg = idx & 31;            // 4-float segment along m
        float4 v = *reinterpret_cast<const float4*>(eP + row * 132 + seg * 4);
        int oc = n0 + row;
        float s = g_bns[oc], t = g_bnb[oc];
        float z0 = v.x * s + t, z1 = v.y * s + t, z2 = v.z * s + t, z3 = v.w * s + t;
        float4 o4;
        o4.x = z0 / (1.0f + __expf(-z0));
        o4.y = z1 / (1.0f + __expf(-z1));
        o4.z = z2 / (1.0f + __expf(-z2));
        o4.w = z3 / (1.0f + __expf(-z3));
        *reinterpret_cast<float4*>(out + (((size_t)(b * 512 + oc)) << 12) + m0 + seg * 4) = o4;
    }
}

// ----------------------------------------------------------------------------
// Launch
// ----------------------------------------------------------------------------
extern "C" void kernel_launch(void* const* d_in, const int* in_sizes, int n_in,
                              void* d_out, int out_size) {
    const float* x      = (const float*)d_in[0];
    const float* w1     = (const float*)d_in[1];
    const float* w2     = (const float*)d_in[2];
    const float* conv_w = (const float*)d_in[3];
    const float* gamma  = (const float*)d_in[4];
    const float* beta   = (const float*)d_in[5];
    const float* mean   = (const float*)d_in[6];
    const float* var    = (const float*)d_in[7];
    float* out = (float*)d_out;
    (void)in_sizes; (void)n_in; (void)out_size;

    cudaFuncSetAttribute(k_gemm, cudaFuncAttributeMaxDynamicSharedMemorySize, SMEM_SZ);

    k_zero<<<24, 256>>>();
    k_wavelet<<<dim3(128, 8, 8), 256>>>(x);
    k_mlp<<<9, 256>>>(w1, w2, gamma, beta, mean, var);
    k_weff<<<16384, 256>>>(conv_w);
    k_gemm<<<dim3(4, 32, 8), 256, SMEM_SZ>>>(out);
}

// round 4
// speedup vs baseline: 1.0294x; 1.0294x over previous
#include <cuda_runtime.h>
#include <cstdint>
#include <math.h>

#define DI __device__ __forceinline__

// ----------------------------------------------------------------------------
// Device scratch (no cudaMalloc allowed)
// ----------------------------------------------------------------------------
__device__ float g_fused[8ull * 4096ull * 1024ull];  // [b][hw2][1024 ch], tf32-rounded
__device__ float g_weff [8ull * 512ull  * 1024ull];  // [b][o][c],         tf32-rounded
__device__ float g_scale[8 * 1024];                  // per-(b,ch) gate (1.0 for LL)
__device__ float g_sum  [8 * 768];                   // hf channel sums
__device__ float g_bns  [512];                       // folded BN scale
__device__ float g_bnb  [512];                       // folded BN bias

// ----------------------------------------------------------------------------
// Helpers (baseline PTX only — no tcgen05/TMA on compute_103 non-'a' target)
// ----------------------------------------------------------------------------
DI uint32_t smem_u32(const void* p) {
    uint32_t a;
    asm("{ .reg .u64 t; cvta.to.shared.u64 t, %1; cvt.u32.u64 %0, t; }" : "=r"(a) : "l"(p));
    return a;
}
DI float tf32r(float x) {
    uint32_t u;
    asm("cvt.rna.tf32.f32 %0, %1;" : "=r"(u) : "f"(x));
    return __uint_as_float(u);
}
DI uint32_t sw128(uint32_t o) { return o ^ ((o >> 3) & 0x70u); }

DI void cpasync16(uint32_t dst, const float* src) {
    asm volatile("cp.async.cg.shared.global [%0], [%1], 16;"
                 :: "r"(dst), "l"(__cvta_generic_to_global(src)) : "memory");
}
DI void cp_commit() { asm volatile("cp.async.commit_group;" ::: "memory"); }
template <int N> DI void cp_wait() { asm volatile("cp.async.wait_group %0;" :: "n"(N) : "memory"); }

// tf32 HMMA: D[16x8] += A[16x8] * B[8x8]
DI void mma8(float* c, const uint32_t* a, const uint32_t* b) {
    asm volatile(
        "mma.sync.aligned.m16n8k8.row.col.f32.tf32.tf32.f32 "
        "{%0,%1,%2,%3}, {%4,%5,%6,%7}, {%8,%9}, {%0,%1,%2,%3};"
        : "+f"(c[0]), "+f"(c[1]), "+f"(c[2]), "+f"(c[3])
        : "r"(a[0]), "r"(a[1]), "r"(a[2]), "r"(a[3]), "r"(b[0]), "r"(b[1]));
}

// ----------------------------------------------------------------------------
// K0: zero the hf channel-sum accumulator
// ----------------------------------------------------------------------------
__global__ void k_zero() {
    int i = blockIdx.x * 256 + threadIdx.x;
    if (i < 8 * 768) g_sum[i] = 0.0f;
}

// ----------------------------------------------------------------------------
// K1: Haar DWT -> g_fused [b][hw2][1024] + hf channel sums
// grid (128 pos-tiles, 8 c-tiles, 8 b), 256 threads
// ----------------------------------------------------------------------------
__global__ __launch_bounds__(256) void k_wavelet(const float* __restrict__ x) {
    const int b = blockIdx.z, c0 = blockIdx.y * 32, p0 = blockIdx.x * 32;
    const int tid = threadIdx.x, lane = tid & 31, w = tid >> 5;

    __shared__ float sLL[32][33];
    __shared__ float sHF[3][32][33];

#pragma unroll
    for (int it = 0; it < 4; ++it) {
        int cc = it * 8 + w;
        int c = c0 + cc;
        int hw2 = p0 + lane;
        int h2 = hw2 >> 6, w2 = hw2 & 63;
        const float* xr = x + (((size_t)(b * 256 + c) * 128 + 2 * h2) * 128 + 2 * w2);
        float2 t0 = *reinterpret_cast<const float2*>(xr);
        float2 t1 = *reinterpret_cast<const float2*>(xr + 128);
        float ll = 0.5f * (t0.x + t0.y + t1.x + t1.y);
        float lh = 0.5f * (t0.x + t0.y - t1.x - t1.y);
        float hl = 0.5f * (t0.x - t0.y + t1.x - t1.y);
        float hh = 0.5f * (t0.x - t0.y - t1.x + t1.y);
        sLL[cc][lane] = ll;
        sHF[0][cc][lane] = lh;
        sHF[1][cc][lane] = hl;
        sHF[2][cc][lane] = hh;
        float slh = lh, shl = hl, shh = hh;
#pragma unroll
        for (int off = 16; off; off >>= 1) {
            slh += __shfl_down_sync(0xffffffffu, slh, off);
            shl += __shfl_down_sync(0xffffffffu, shl, off);
            shh += __shfl_down_sync(0xffffffffu, shh, off);
        }
        if (lane == 0) {
            atomicAdd(&g_sum[b * 768 + 3 * c + 0], slh);
            atomicAdd(&g_sum[b * 768 + 3 * c + 1], shl);
            atomicAdd(&g_sum[b * 768 + 3 * c + 2], shh);
        }
    }
    __syncthreads();

    // Transposed, coalesced write into [hw][channel] layout (tf32-pre-rounded)
#pragma unroll
    for (int it = 0; it < 16; ++it) {
        int wdx = it * 256 + tid;
        int pp = wdx >> 7, cl = wdx & 127;
        float v;
        int col;
        if (cl < 32) {
            v = sLL[cl][pp];
            col = c0 + cl;
        } else {
            int k = cl - 32;
            int cc = k / 3;
            int sb = k - 3 * cc;
            v = sHF[sb][cc][pp];
            col = 256 + 3 * c0 + k;
        }
        g_fused[((size_t)(b * 4096 + p0 + pp) << 10) + col] = tf32r(v);
    }
}

// ----------------------------------------------------------------------------
// K2: blocks 0..7 = per-batch MLP gate; block 8 = folded BN params
// ----------------------------------------------------------------------------
__global__ __launch_bounds__(256) void k_mlp(const float* __restrict__ w1, const float* __restrict__ w2,
                                             const float* __restrict__ gamma, const float* __restrict__ beta,
                                             const float* __restrict__ mean, const float* __restrict__ var) {
    int tid = threadIdx.x;
    if (blockIdx.x == 8) {
        for (int o = tid; o < 512; o += 256) {
            float s = gamma[o] * rsqrtf(var[o] + 1e-5f);
            g_bns[o] = s;
            g_bnb[o] = beta[o] - mean[o] * s;
        }
        return;
    }
    int b = blockIdx.x;
    __shared__ float s_mean[768];
    __shared__ float s_y1[48];
    for (int c = tid; c < 768; c += 256) s_mean[c] = g_sum[b * 768 + c] * (1.0f / 4096.0f);
    __syncthreads();
    int w = tid >> 5, lane = tid & 31;
#pragma unroll 1
    for (int i = 0; i < 6; i++) {
        int m = w + 8 * i;
        float acc = 0.f;
        for (int j = 0; j < 24; j++) {
            int c = lane + 32 * j;
            acc += s_mean[c] * w1[m * 768 + c];
        }
#pragma unroll
        for (int off = 16; off; off >>= 1) acc += __shfl_down_sync(0xffffffffu, acc, off);
        if (lane == 0) s_y1[m] = fmaxf(acc, 0.f);
    }
    __syncthreads();
    g_scale[b * 1024 + tid] = 1.0f;  // LL channels unscaled
    for (int c = tid; c < 768; c += 256) {
        float acc = 0.f;
#pragma unroll
        for (int m = 0; m < 48; m++) acc += s_y1[m] * w2[c * 48 + m];
        g_scale[b * 1024 + 256 + c] = 1.0f / (1.0f + expf(-acc));
    }
}

// ----------------------------------------------------------------------------
// K3: W_eff[b][o][c] = conv_w[o][c] * scale[b][c], tf32-rounded
// ----------------------------------------------------------------------------
__global__ __launch_bounds__(256) void k_weff(const float* __restrict__ conv_w) {
    int idx = blockIdx.x * 256 + threadIdx.x;  // < 8*512*1024 = 2^22
    int b = idx >> 19;
    int oc = idx & 524287;
    int c = idx & 1023;
    g_weff[idx] = tf32r(conv_w[oc] * g_scale[b * 1024 + c]);
}

// ----------------------------------------------------------------------------
// K4: tf32 mma.sync GEMM. CTA tile 128M x 256N x 32K, 512 threads (16 warps,
//     2m x 8n of 64x32 warp tiles), 3-stage cp.async pipeline, SW128 smem
//     (conflict-free fragment LDS), smem-transposed epilogue + BN + SiLU.
//     grid (2 ntile, 32 mtile, 8 b) = 512 CTAs.
// ----------------------------------------------------------------------------
static constexpr int A_BYTES   = 128 * 32 * 4;        // 16 KB
static constexpr int B_BYTES   = 256 * 32 * 4;        // 32 KB
static constexpr int STAGE_SZ  = A_BYTES + B_BYTES;   // 48 KB
static constexpr int SMEM_SZ   = 3 * STAGE_SZ;        // 147456

__global__ __launch_bounds__(512, 1) void k_gemm(float* __restrict__ out) {
    extern __shared__ __align__(1024) char smem[];
    const uint32_t sb = smem_u32(smem);
    const int tid = threadIdx.x, lane = tid & 31, wid = tid >> 5;
    const int wm = wid & 1, wn = wid >> 1;           // warp grid 2(m) x 8(n)
    const int rq = lane >> 2, qq = lane & 3;
    const int b = blockIdx.z, m0 = blockIdx.y * 128, n0 = blockIdx.x * 256;

    const float* Ab = g_fused + (((size_t)(b * 4096 + m0)) << 10);
    const float* Bb = g_weff  + (((size_t)(b * 512  + n0)) << 10);

    auto produce = [&](int step) {
        int s = step % 3;
        int kc = step * 32;
        uint32_t da = sb + s * STAGE_SZ;
        uint32_t db = da + A_BYTES;
#pragma unroll
        for (int j = 0; j < 2; j++) {   // A: 1024 16B-chunks
            uint32_t q = tid + 512 * j;
            cpasync16(da + sw128(q * 16), Ab + ((size_t)(q >> 3) << 10) + kc + ((q & 7) << 2));
        }
#pragma unroll
        for (int j = 0; j < 4; j++) {   // B: 2048 16B-chunks
            uint32_t q = tid + 512 * j;
            cpasync16(db + sw128(q * 16), Bb + ((size_t)(q >> 3) << 10) + kc + ((q & 7) << 2));
        }
        cp_commit();
    };

    produce(0); produce(1);

    float acc[4][4][4];
#pragma unroll
    for (int i = 0; i < 4; i++)
#pragma unroll
        for (int j = 0; j < 4; j++)
#pragma unroll
            for (int r = 0; r < 4; r++) acc[i][j][r] = 0.f;

    // per-thread float-index bases into the row-major [row][32f] tiles
    const int arow = ((wm * 64 + rq) << 5) + qq;
    const int brow = ((wn * 32 + rq) << 5) + qq;

#pragma unroll 1
    for (int kt = 0; kt < 32; ++kt) {
        if (kt < 30) {
            cp_wait<1>();
            __syncthreads();
            produce(kt + 2);
        } else {
            cp_wait<0>();
            __syncthreads();
        }

        int s = kt % 3;
        const float* sA  = reinterpret_cast<const float*>(smem + s * STAGE_SZ);
        const float* sBt = reinterpret_cast<const float*>(smem + s * STAGE_SZ + A_BYTES);

#pragma unroll
        for (int ks = 0; ks < 4; ++ks) {
            const int x0 = ((2 * ks) ^ rq) << 2;       // SW128 chunk XOR with row&7
            const int x1 = ((2 * ks + 1) ^ rq) << 2;
            uint32_t a[4][4], bf[4][2];
#pragma unroll
            for (int i = 0; i < 4; i++) {
                int base = arow + (i << 9);            // +16 rows = +512 floats
                a[i][0] = __float_as_uint(sA[base + x0]);
                a[i][1] = __float_as_uint(sA[base + 256 + x0]);  // +8 rows
                a[i][2] = __float_as_uint(sA[base + x1]);
                a[i][3] = __float_as_uint(sA[base + 256 + x1]);
            }
#pragma unroll
            for (int j = 0; j < 4; j++) {
                int base = brow + (j << 8);            // +8 rows = +256 floats
                bf[j][0] = __float_as_uint(sBt[base + x0]);
                bf[j][1] = __float_as_uint(sBt[base + x1]);
            }
#pragma unroll
            for (int i = 0; i < 4; i++)
#pragma unroll
                for (int j = 0; j < 4; j++) mma8(acc[i][j], a[i], bf[j]);
        }
    }

    // ---- epilogue: transpose through smem, fused BN + SiLU, coalesced STG ----
    __syncthreads();
    float* eP = reinterpret_cast<float*>(smem);        // [n 256][m 128], stride 132
#pragma unroll
    for (int i = 0; i < 4; i++) {
        int m = wm * 64 + i * 16 + rq;
#pragma unroll
        for (int j = 0; j < 4; j++) {
            int n = wn * 32 + j * 8 + 2 * qq;
            eP[n * 132 + m]           = acc[i][j][0];
            eP[(n + 1) * 132 + m]     = acc[i][j][1];
            eP[n * 132 + m + 8]       = acc[i][j][2];
            eP[(n + 1) * 132 + m + 8] = acc[i][j][3];
        }
    }
    __syncthreads();

#pragma unroll 1
    for (int idx = tid; idx < 256 * 32; idx += 512) {
        int row = idx >> 5;            // local output channel (uniform per warp)
        int seg = idx & 31;            // 4-float segment along m
        float4 v = *reinterpret_cast<const float4*>(eP + row * 132 + seg * 4);
        int oc = n0 + row;
        float s = g_bns[oc], t = g_bnb[oc];
        float z0 = v.x * s + t, z1 = v.y * s + t, z2 = v.z * s + t, z3 = v.w * s + t;
        float4 o4;
        o4.x = z0 / (1.0f + __expf(-z0));
        o4.y = z1 / (1.0f + __expf(-z1));
        o4.z = z2 / (1.0f + __expf(-z2));
        o4.w = z3 / (1.0f + __expf(-z3));
        *reinterpret_cast<float4*>(out + (((size_t)(b * 512 + oc)) << 12) + m0 + seg * 4) = o4;
    }
}

// ----------------------------------------------------------------------------
// Launch
// ----------------------------------------------------------------------------
extern "C" void kernel_launch(void* const* d_in, const int* in_sizes, int n_in,
                              void* d_out, int out_size) {
    const float* x      = (const float*)d_in[0];
    const float* w1     = (const float*)d_in[1];
    const float* w2     = (const float*)d_in[2];
    const float* conv_w = (const float*)d_in[3];
    const float* gamma  = (const float*)d_in[4];
    const float* beta   = (const float*)d_in[5];
    const float* mean   = (const float*)d_in[6];
    const float* var    = (const float*)d_in[7];
    float* out = (float*)d_out;
    (void)in_sizes; (void)n_in; (void)out_size;

    cudaFuncSetAttribute(k_gemm, cudaFuncAttributeMaxDynamicSharedMemorySize, SMEM_SZ);

    k_zero<<<24, 256>>>();
    k_wavelet<<<dim3(128, 8, 8), 256>>>(x);
    k_mlp<<<9, 256>>>(w1, w2, gamma, beta, mean, var);
    k_weff<<<16384, 256>>>(conv_w);
    k_gemm<<<dim3(2, 32, 8), 512, SMEM_SZ>>>(out);
}

// round 5
// speedup vs baseline: 1.4817x; 1.4393x over previous
#include <cuda_runtime.h>
#include <cuda_fp16.h>
#include <cstdint>
#include <math.h>

#define DI __device__ __forceinline__

// ----------------------------------------------------------------------------
// Device scratch (no cudaMalloc allowed)
// ----------------------------------------------------------------------------
__device__ __half g_fused[8ull * 4096ull * 1024ull]; // [b][hw2][1024 ch], fp16
__device__ __half g_weff [8ull * 512ull  * 1024ull]; // [b][o][c],         fp16
__device__ float  g_scale[8 * 1024];                 // per-(b,ch) gate (1.0 for LL)
__device__ float  g_sum  [8 * 768];                  // hf channel sums
__device__ float  g_bns  [512];                      // folded BN scale
__device__ float  g_bnb  [512];                      // folded BN bias

// ----------------------------------------------------------------------------
// Helpers (baseline PTX only — no tcgen05/TMA on compute_103 non-'a' target)
// ----------------------------------------------------------------------------
DI uint32_t sw128(uint32_t o) { return o ^ ((o >> 3) & 0x70u); }

DI void cpasync16(uint32_t dst_off_unused, const void*) {}  // (unused placeholder removed below)

DI void cpa16(uint32_t dst, const void* src) {
    asm volatile("cp.async.cg.shared.global [%0], [%1], 16;"
                 :: "r"(dst), "l"(__cvta_generic_to_global(src)) : "memory");
}
DI void cp_commit() { asm volatile("cp.async.commit_group;" ::: "memory"); }
template <int N> DI void cp_wait() { asm volatile("cp.async.wait_group %0;" :: "n"(N) : "memory"); }

DI uint32_t smem_u32(const void* p) {
    uint32_t a;
    asm("{ .reg .u64 t; cvta.to.shared.u64 t, %1; cvt.u32.u64 %0, t; }" : "=r"(a) : "l"(p));
    return a;
}

// fp16 HMMA with fp32 accumulate: D[16x8] += A[16x16] * B[16x8]
DI void mma16(float* c, const uint32_t* a, const uint32_t* b) {
    asm volatile(
        "mma.sync.aligned.m16n8k16.row.col.f32.f16.f16.f32 "
        "{%0,%1,%2,%3}, {%4,%5,%6,%7}, {%8,%9}, {%0,%1,%2,%3};"
        : "+f"(c[0]), "+f"(c[1]), "+f"(c[2]), "+f"(c[3])
        : "r"(a[0]), "r"(a[1]), "r"(a[2]), "r"(a[3]), "r"(b[0]), "r"(b[1]));
}

// ----------------------------------------------------------------------------
// K0: zero the hf channel-sum accumulator
// ----------------------------------------------------------------------------
__global__ void k_zero() {
    int i = blockIdx.x * 256 + threadIdx.x;
    if (i < 8 * 768) g_sum[i] = 0.0f;
}

// ----------------------------------------------------------------------------
// K1: Haar DWT -> g_fused [b][hw2][1024] (fp16) + hf channel sums
// grid (128 pos-tiles, 8 c-tiles, 8 b), 256 threads
// ----------------------------------------------------------------------------
__global__ __launch_bounds__(256) void k_wavelet(const float* __restrict__ x) {
    const int b = blockIdx.z, c0 = blockIdx.y * 32, p0 = blockIdx.x * 32;
    const int tid = threadIdx.x, lane = tid & 31, w = tid >> 5;

    __shared__ float sLL[32][33];
    __shared__ float sHF[3][32][33];

#pragma unroll
    for (int it = 0; it < 4; ++it) {
        int cc = it * 8 + w;
        int c = c0 + cc;
        int hw2 = p0 + lane;
        int h2 = hw2 >> 6, w2 = hw2 & 63;
        const float* xr = x + (((size_t)(b * 256 + c) * 128 + 2 * h2) * 128 + 2 * w2);
        float2 t0 = *reinterpret_cast<const float2*>(xr);
        float2 t1 = *reinterpret_cast<const float2*>(xr + 128);
        float ll = 0.5f * (t0.x + t0.y + t1.x + t1.y);
        float lh = 0.5f * (t0.x + t0.y - t1.x - t1.y);
        float hl = 0.5f * (t0.x - t0.y + t1.x - t1.y);
        float hh = 0.5f * (t0.x - t0.y - t1.x + t1.y);
        sLL[cc][lane] = ll;
        sHF[0][cc][lane] = lh;
        sHF[1][cc][lane] = hl;
        sHF[2][cc][lane] = hh;
        float slh = lh, shl = hl, shh = hh;
#pragma unroll
        for (int off = 16; off; off >>= 1) {
            slh += __shfl_down_sync(0xffffffffu, slh, off);
            shl += __shfl_down_sync(0xffffffffu, shl, off);
            shh += __shfl_down_sync(0xffffffffu, shh, off);
        }
        if (lane == 0) {
            atomicAdd(&g_sum[b * 768 + 3 * c + 0], slh);
            atomicAdd(&g_sum[b * 768 + 3 * c + 1], shl);
            atomicAdd(&g_sum[b * 768 + 3 * c + 2], shh);
        }
    }
    __syncthreads();

    // Transposed write into [hw][channel] layout (fp16)
#pragma unroll
    for (int it = 0; it < 16; ++it) {
        int wdx = it * 256 + tid;
        int pp = wdx >> 7, cl = wdx & 127;
        float v;
        int col;
        if (cl < 32) {
            v = sLL[cl][pp];
            col = c0 + cl;
        } else {
            int k = cl - 32;
            int cc = k / 3;
            int sb = k - 3 * cc;
            v = sHF[sb][cc][pp];
            col = 256 + 3 * c0 + k;
        }
        g_fused[((size_t)(b * 4096 + p0 + pp) << 10) + col] = __float2half_rn(v);
    }
}

// ----------------------------------------------------------------------------
// K2: blocks 0..7 = per-batch MLP gate; block 8 = folded BN params
// ----------------------------------------------------------------------------
__global__ __launch_bounds__(256) void k_mlp(const float* __restrict__ w1, const float* __restrict__ w2,
                                             const float* __restrict__ gamma, const float* __restrict__ beta,
                                             const float* __restrict__ mean, const float* __restrict__ var) {
    int tid = threadIdx.x;
    if (blockIdx.x == 8) {
        for (int o = tid; o < 512; o += 256) {
            float s = gamma[o] * rsqrtf(var[o] + 1e-5f);
            g_bns[o] = s;
            g_bnb[o] = beta[o] - mean[o] * s;
        }
        return;
    }
    int b = blockIdx.x;
    __shared__ float s_mean[768];
    __shared__ float s_y1[48];
    for (int c = tid; c < 768; c += 256) s_mean[c] = g_sum[b * 768 + c] * (1.0f / 4096.0f);
    __syncthreads();
    int w = tid >> 5, lane = tid & 31;
#pragma unroll 1
    for (int i = 0; i < 6; i++) {
        int m = w + 8 * i;
        float acc = 0.f;
        for (int j = 0; j < 24; j++) {
            int c = lane + 32 * j;
            acc += s_mean[c] * w1[m * 768 + c];
        }
#pragma unroll
        for (int off = 16; off; off >>= 1) acc += __shfl_down_sync(0xffffffffu, acc, off);
        if (lane == 0) s_y1[m] = fmaxf(acc, 0.f);
    }
    __syncthreads();
    g_scale[b * 1024 + tid] = 1.0f;  // LL channels unscaled
    for (int c = tid; c < 768; c += 256) {
        float acc = 0.f;
#pragma unroll
        for (int m = 0; m < 48; m++) acc += s_y1[m] * w2[c * 48 + m];
        g_scale[b * 1024 + 256 + c] = 1.0f / (1.0f + expf(-acc));
    }
}

// ----------------------------------------------------------------------------
// K3: W_eff[b][o][c] = conv_w[o][c] * scale[b][c]  (fp16, half2 stores)
// ----------------------------------------------------------------------------
__global__ __launch_bounds__(256) void k_weff(const float* __restrict__ conv_w) {
    int idx = blockIdx.x * 256 + threadIdx.x;   // < 8*512*512 = 2^21 half2 elems
    int b  = idx >> 18;                         // 512*512 half2 per batch
    int oc2 = idx & 262143;                     // half2 index within batch
    int c2  = idx & 511;                        // half2 index within row (1024/2)
    float s0 = g_scale[b * 1024 + 2 * c2];
    float s1 = g_scale[b * 1024 + 2 * c2 + 1];
    float w0 = conv_w[2 * oc2];
    float w1v = conv_w[2 * oc2 + 1];
    reinterpret_cast<__half2*>(g_weff)[idx] = __floats2half2_rn(w0 * s0, w1v * s1);
}

// ----------------------------------------------------------------------------
// K4: fp16 mma.sync GEMM (fp32 accum). CTA tile 128M x 256N x 64K, 512 threads
//     (16 warps, 2m x 8n of 64x32 warp tiles), 3-stage cp.async pipeline,
//     SW128 smem (conflict-free), smem-transposed epilogue + BN + SiLU.
//     grid (2 ntile, 32 mtile, 8 b) = 512 CTAs.
// ----------------------------------------------------------------------------
static constexpr int A_BYTES  = 128 * 64 * 2;         // 16 KB
static constexpr int B_BYTES  = 256 * 64 * 2;         // 32 KB
static constexpr int STAGE_SZ = A_BYTES + B_BYTES;    // 48 KB
static constexpr int SMEM_SZ  = 3 * STAGE_SZ;         // 147456

__global__ __launch_bounds__(512, 1) void k_gemm(float* __restrict__ out) {
    extern __shared__ __align__(1024) char smem[];
    const uint32_t sb = smem_u32(smem);
    const int tid = threadIdx.x, lane = tid & 31, wid = tid >> 5;
    const int wm = wid & 1, wn = wid >> 1;           // warp grid 2(m) x 8(n)
    const int rq = lane >> 2, qq = lane & 3;
    const int b = blockIdx.z, m0 = blockIdx.y * 128, n0 = blockIdx.x * 256;

    const __half* Ab = g_fused + (((size_t)(b * 4096 + m0)) << 10);
    const __half* Bb = g_weff  + (((size_t)(b * 512  + n0)) << 10);

    auto produce = [&](int step) {
        int s = step % 3;
        int kc = step * 64;                           // half offset within K
        uint32_t da = sb + s * STAGE_SZ;
        uint32_t db = da + A_BYTES;
#pragma unroll
        for (int j = 0; j < 2; j++) {   // A: 1024 16B-chunks (128 rows x 8)
            uint32_t q = tid + 512 * j;
            cpa16(da + sw128(q * 16), Ab + ((size_t)(q >> 3) << 10) + kc + ((q & 7) << 3));
        }
#pragma unroll
        for (int j = 0; j < 4; j++) {   // B: 2048 16B-chunks (256 rows x 8)
            uint32_t q = tid + 512 * j;
            cpa16(db + sw128(q * 16), Bb + ((size_t)(q >> 3) << 10) + kc + ((q & 7) << 3));
        }
        cp_commit();
    };

    produce(0); produce(1);

    float acc[4][4][4];
#pragma unroll
    for (int i = 0; i < 4; i++)
#pragma unroll
        for (int j = 0; j < 4; j++)
#pragma unroll
            for (int r = 0; r < 4; r++) acc[i][j][r] = 0.f;

#pragma unroll 1
    for (int kt = 0; kt < 16; ++kt) {
        if (kt < 14) {
            cp_wait<1>();
            __syncthreads();
            produce(kt + 2);
        } else {
            cp_wait<0>();
            __syncthreads();
        }

        const char* sA = smem + (kt % 3) * STAGE_SZ;
        const char* sB = sA + A_BYTES;

#pragma unroll
        for (int ks = 0; ks < 4; ++ks) {
            // byte offsets within a 128B row; SW128 XORs 16B-chunk with (row&7)=rq
            const int xb0 = (((2 * ks)     ^ rq) << 4) + (qq << 2);
            const int xb1 = (((2 * ks + 1) ^ rq) << 4) + (qq << 2);
            uint32_t a[4][4], bf[4][2];
#pragma unroll
            for (int i = 0; i < 4; i++) {
                int rb = (wm * 64 + i * 16 + rq) << 7;         // row * 128B
                a[i][0] = *reinterpret_cast<const uint32_t*>(sA + rb + xb0);
                a[i][1] = *reinterpret_cast<const uint32_t*>(sA + rb + 1024 + xb0);  // +8 rows
                a[i][2] = *reinterpret_cast<const uint32_t*>(sA + rb + xb1);
                a[i][3] = *reinterpret_cast<const uint32_t*>(sA + rb + 1024 + xb1);
            }
#pragma unroll
            for (int j = 0; j < 4; j++) {
                int rb = (wn * 32 + j * 8 + rq) << 7;
                bf[j][0] = *reinterpret_cast<const uint32_t*>(sB + rb + xb0);
                bf[j][1] = *reinterpret_cast<const uint32_t*>(sB + rb + xb1);
            }
#pragma unroll
            for (int i = 0; i < 4; i++)
#pragma unroll
                for (int j = 0; j < 4; j++) mma16(acc[i][j], a[i], bf[j]);
        }
    }

    // ---- epilogue: transpose through smem, fused BN + SiLU, coalesced STG ----
    __syncthreads();
    float* eP = reinterpret_cast<float*>(smem);        // [n 256][m 128], stride 132
#pragma unroll
    for (int i = 0; i < 4; i++) {
        int m = wm * 64 + i * 16 + rq;
#pragma unroll
        for (int j = 0; j < 4; j++) {
            int n = wn * 32 + j * 8 + 2 * qq;
            eP[n * 132 + m]           = acc[i][j][0];
            eP[(n + 1) * 132 + m]     = acc[i][j][1];
            eP[n * 132 + m + 8]       = acc[i][j][2];
            eP[(n + 1) * 132 + m + 8] = acc[i][j][3];
        }
    }
    __syncthreads();

#pragma unroll 1
    for (int idx = tid; idx < 256 * 32; idx += 512) {
        int row = idx >> 5;            // local output channel (uniform per warp)
        int seg = idx & 31;            // 4-float segment along m
        float4 v = *reinterpret_cast<const float4*>(eP + row * 132 + seg * 4);
        int oc = n0 + row;
        float s = g_bns[oc], t = g_bnb[oc];
        float z0 = v.x * s + t, z1 = v.y * s + t, z2 = v.z * s + t, z3 = v.w * s + t;
        float4 o4;
        o4.x = z0 / (1.0f + __expf(-z0));
        o4.y = z1 / (1.0f + __expf(-z1));
        o4.z = z2 / (1.0f + __expf(-z2));
        o4.w = z3 / (1.0f + __expf(-z3));
        *reinterpret_cast<float4*>(out + (((size_t)(b * 512 + oc)) << 12) + m0 + seg * 4) = o4;
    }
}

// ----------------------------------------------------------------------------
// Launch
// ----------------------------------------------------------------------------
extern "C" void kernel_launch(void* const* d_in, const int* in_sizes, int n_in,
                              void* d_out, int out_size) {
    const float* x      = (const float*)d_in[0];
    const float* w1     = (const float*)d_in[1];
    const float* w2     = (const float*)d_in[2];
    const float* conv_w = (const float*)d_in[3];
    const float* gamma  = (const float*)d_in[4];
    const float* beta   = (const float*)d_in[5];
    const float* mean   = (const float*)d_in[6];
    const float* var    = (const float*)d_in[7];
    float* out = (float*)d_out;
    (void)in_sizes; (void)n_in; (void)out_size;

    cudaFuncSetAttribute(k_gemm, cudaFuncAttributeMaxDynamicSharedMemorySize, SMEM_SZ);

    k_zero<<<24, 256>>>();
    k_wavelet<<<dim3(128, 8, 8), 256>>>(x);
    k_mlp<<<9, 256>>>(w1, w2, gamma, beta, mean, var);
    k_weff<<<8192, 256>>>(conv_w);
    k_gemm<<<dim3(2, 32, 8), 512, SMEM_SZ>>>(out);
}

// round 6
// speedup vs baseline: 1.4826x; 1.0006x over previous
#include <cuda_runtime.h>
#include <cuda_fp16.h>
#include <cstdint>
#include <math.h>

#define DI __device__ __forceinline__

// ----------------------------------------------------------------------------
// Device scratch (no cudaMalloc allowed). K-major tiled, SW128-preswizzled:
//   g_fused: [b][kt=16][m=4096][64ch]  (128B rows, swizzled within 1KB blocks)
//   g_weff : [b][kt=16][o=512 ][64ch]
// ----------------------------------------------------------------------------
__device__ __half g_fused[8ull * 16ull * 4096ull * 64ull];
__device__ __half g_weff [8ull * 16ull * 512ull  * 64ull];
__device__ float  g_scale[8 * 1024];                 // per-(b,ch) gate (1.0 for LL)
__device__ float  g_sum  [8 * 768];                  // hf channel sums (zero-init; re-zeroed each call)
__device__ float  g_bns  [512];                      // folded BN scale
__device__ float  g_bnb  [512];                      // folded BN bias

// ----------------------------------------------------------------------------
// Helpers (baseline PTX only — no tcgen05 / no 'a'-gated features)
// ----------------------------------------------------------------------------
DI uint32_t sw128(uint32_t o) { return o ^ ((o >> 3) & 0x70u); }

DI uint32_t smem_u32(const void* p) {
    uint32_t a;
    asm("{ .reg .u64 t; cvta.to.shared.u64 t, %1; cvt.u32.u64 %0, t; }" : "=r"(a) : "l"(p));
    return a;
}
// global byte offset for (row, col2B) in a preswizzled [rows][64ch] tile
DI uint32_t tile_off(uint32_t row, uint32_t colbyte) {
    uint32_t off = row * 128u + colbyte;
    return (off & ~1023u) + sw128(off & 1023u);
}

DI void mbar_init(uint32_t mbar, uint32_t cnt) {
    asm volatile("mbarrier.init.shared.b64 [%0], %1;" :: "r"(mbar), "r"(cnt) : "memory");
}
DI void mbar_expect_tx(uint32_t mbar, uint32_t bytes) {
    asm volatile("mbarrier.arrive.expect_tx.shared.b64 _, [%0], %1;"
                 :: "r"(mbar), "r"(bytes) : "memory");
}
DI void mbar_wait(uint32_t mbar, uint32_t parity) {
    asm volatile(
        "{\n\t.reg .pred P1;\n\t"
        "LAB_WAIT_%=:\n\t"
        "mbarrier.try_wait.parity.acquire.cta.shared::cta.b64 P1, [%0], %1, 0x989680;\n\t"
        "@P1 bra.uni LAB_DONE_%=;\n\t"
        "bra.uni LAB_WAIT_%=;\n\t"
        "LAB_DONE_%=:\n\t}"
        :: "r"(mbar), "r"(parity) : "memory");
}
// 1-D bulk async copy global -> shared (sm_90 baseline; single thread issues)
DI void bulk_g2s(uint32_t dst, const void* src, uint32_t bytes, uint32_t mbar) {
    asm volatile(
        "cp.async.bulk.shared::cluster.global.mbarrier::complete_tx::bytes [%0], [%1], %2, [%3];"
        :: "r"(dst), "l"(__cvta_generic_to_global(src)), "r"(bytes), "r"(mbar) : "memory");
}

// fp16 HMMA with fp32 accumulate: D[16x8] += A[16x16] * B[16x8]
DI void mma16(float* c, const uint32_t* a, const uint32_t* b) {
    asm volatile(
        "mma.sync.aligned.m16n8k16.row.col.f32.f16.f16.f32 "
        "{%0,%1,%2,%3}, {%4,%5,%6,%7}, {%8,%9}, {%0,%1,%2,%3};"
        : "+f"(c[0]), "+f"(c[1]), "+f"(c[2]), "+f"(c[3])
        : "r"(a[0]), "r"(a[1]), "r"(a[2]), "r"(a[3]), "r"(b[0]), "r"(b[1]));
}

// ----------------------------------------------------------------------------
// K1: Haar DWT -> preswizzled K-major g_fused + hf channel sums
// grid (128 pos-tiles, 8 c-tiles, 8 b), 256 threads
// ----------------------------------------------------------------------------
__global__ __launch_bounds__(256) void k_wavelet(const float* __restrict__ x) {
    const int b = blockIdx.z, c0 = blockIdx.y * 32, p0 = blockIdx.x * 32;
    const int tid = threadIdx.x, lane = tid & 31, w = tid >> 5;

    __shared__ float sLL[32][33];
    __shared__ float sHF[3][32][33];

#pragma unroll
    for (int it = 0; it < 4; ++it) {
        int cc = it * 8 + w;
        int c = c0 + cc;
        int hw2 = p0 + lane;
        int h2 = hw2 >> 6, w2 = hw2 & 63;
        const float* xr = x + (((size_t)(b * 256 + c) * 128 + 2 * h2) * 128 + 2 * w2);
        float2 t0 = *reinterpret_cast<const float2*>(xr);
        float2 t1 = *reinterpret_cast<const float2*>(xr + 128);
        float ll = 0.5f * (t0.x + t0.y + t1.x + t1.y);
        float lh = 0.5f * (t0.x + t0.y - t1.x - t1.y);
        float hl = 0.5f * (t0.x - t0.y + t1.x - t1.y);
        float hh = 0.5f * (t0.x - t0.y - t1.x + t1.y);
        sLL[cc][lane] = ll;
        sHF[0][cc][lane] = lh;
        sHF[1][cc][lane] = hl;
        sHF[2][cc][lane] = hh;
        float slh = lh, shl = hl, shh = hh;
#pragma unroll
        for (int off = 16; off; off >>= 1) {
            slh += __shfl_down_sync(0xffffffffu, slh, off);
            shl += __shfl_down_sync(0xffffffffu, shl, off);
            shh += __shfl_down_sync(0xffffffffu, shh, off);
        }
        if (lane == 0) {
            atomicAdd(&g_sum[b * 768 + 3 * c + 0], slh);
            atomicAdd(&g_sum[b * 768 + 3 * c + 1], shl);
            atomicAdd(&g_sum[b * 768 + 3 * c + 2], shh);
        }
    }
    __syncthreads();

    // Write into K-major preswizzled layout (fp16)
#pragma unroll
    for (int it = 0; it < 16; ++it) {
        int wdx = it * 256 + tid;
        int pp = wdx >> 7, cl = wdx & 127;
        float v;
        int col;
        if (cl < 32) {
            v = sLL[cl][pp];
            col = c0 + cl;
        } else {
            int k = cl - 32;
            int cc = k / 3;
            int sb = k - 3 * cc;
            v = sHF[sb][cc][pp];
            col = 256 + 3 * c0 + k;
        }
        int m = p0 + pp;
        int kt = col >> 6, c6 = col & 63;
        char* base = reinterpret_cast<char*>(g_fused) + ((size_t)(b * 16 + kt) * 4096) * 128;
        *reinterpret_cast<__half*>(base + tile_off(m, c6 * 2)) = __float2half_rn(v);
    }
}

// ----------------------------------------------------------------------------
// K2: blocks 0..7 = per-batch MLP gate; block 8 = folded BN params
// ----------------------------------------------------------------------------
__global__ __launch_bounds__(256) void k_mlp(const float* __restrict__ w1, const float* __restrict__ w2,
                                             const float* __restrict__ gamma, const float* __restrict__ beta,
                                             const float* __restrict__ mean, const float* __restrict__ var) {
    int tid = threadIdx.x;
    if (blockIdx.x == 8) {
        for (int o = tid; o < 512; o += 256) {
            float s = gamma[o] * rsqrtf(var[o] + 1e-5f);
            g_bns[o] = s;
            g_bnb[o] = beta[o] - mean[o] * s;
        }
        return;
    }
    int b = blockIdx.x;
    __shared__ float s_mean[768];
    __shared__ float s_y1[48];
    for (int c = tid; c < 768; c += 256) s_mean[c] = g_sum[b * 768 + c] * (1.0f / 4096.0f);
    __syncthreads();
    int w = tid >> 5, lane = tid & 31;
#pragma unroll 1
    for (int i = 0; i < 6; i++) {
        int m = w + 8 * i;
        float acc = 0.f;
        for (int j = 0; j < 24; j++) {
            int c = lane + 32 * j;
            acc += s_mean[c] * w1[m * 768 + c];
        }
#pragma unroll
        for (int off = 16; off; off >>= 1) acc += __shfl_down_sync(0xffffffffu, acc, off);
        if (lane == 0) s_y1[m] = fmaxf(acc, 0.f);
    }
    __syncthreads();
    g_scale[b * 1024 + tid] = 1.0f;  // LL channels unscaled
    for (int c = tid; c < 768; c += 256) {
        float acc = 0.f;
#pragma unroll
        for (int m = 0; m < 48; m++) acc += s_y1[m] * w2[c * 48 + m];
        g_scale[b * 1024 + 256 + c] = 1.0f / (1.0f + expf(-acc));
    }
}

// ----------------------------------------------------------------------------
// K3: W_eff -> preswizzled K-major g_weff; also re-zero g_sum for next call
// ----------------------------------------------------------------------------
__global__ __launch_bounds__(256) void k_weff(const float* __restrict__ conv_w) {
    int idx = blockIdx.x * 256 + threadIdx.x;   // 2^21 half2 elems total
    int b   = idx >> 18;
    int r   = idx & 262143;
    int kt  = r >> 14;
    int r2  = r & 16383;
    int o   = r2 >> 5;
    int c2  = r2 & 31;                          // half2 within 64-col row
    int c   = kt * 64 + 2 * c2;
    float s0 = g_scale[b * 1024 + c];
    float s1 = g_scale[b * 1024 + c + 1];
    __half2 v = __floats2half2_rn(conv_w[o * 1024 + c] * s0, conv_w[o * 1024 + c + 1] * s1);
    char* base = reinterpret_cast<char*>(g_weff) + ((size_t)(b * 16 + kt) * 512) * 128;
    *reinterpret_cast<__half2*>(base + tile_off(o, c2 * 4)) = v;

    if (blockIdx.x == 0) {   // g_sum consumed by k_mlp already; zero for next call
        for (int i = threadIdx.x; i < 8 * 768; i += 256) g_sum[i] = 0.f;
    }
}

// ----------------------------------------------------------------------------
// K4: fp16 mma.sync GEMM fed by cp.async.bulk + mbarrier (3-stage).
//     CTA tile 128M x 256N x 64K, 512 threads (16 warps, 2m x 8n, 64x32 warp
//     tiles), SW128 smem (preswizzled in gmem, linear bulk copy), smem-
//     transposed epilogue + BN + SiLU.  grid (2 ntile, 32 mtile, 8 b).
// ----------------------------------------------------------------------------
static constexpr int A_BYTES = 128 * 64 * 2;          // 16 KB
static constexpr int B_BYTES = 256 * 64 * 2;          // 32 KB
static constexpr int STAGE   = A_BYTES + B_BYTES;     // 48 KB
static constexpr int SM_OFF  = 1024;                  // mbars live below
static constexpr int SMEM_SZ = SM_OFF + 3 * STAGE;    // 148480

__global__ __launch_bounds__(512, 1) void k_gemm(float* __restrict__ out) {
    extern __shared__ __align__(1024) char smem[];
    const uint32_t sb = smem_u32(smem);
    const int tid = threadIdx.x, lane = tid & 31, wid = tid >> 5;
    const int wm = wid & 1, wn = wid >> 1;            // warp grid 2(m) x 8(n)
    const int rq = lane >> 2, qq = lane & 3;
    const int b = blockIdx.z, m0 = blockIdx.y * 128, n0 = blockIdx.x * 256;

    if (tid == 0) {
        mbar_init(sb + 0, 1);
        mbar_init(sb + 8, 1);
        mbar_init(sb + 16, 1);
    }
    asm volatile("fence.proxy.async.shared::cta;" ::: "memory");
    __syncthreads();

    auto issue = [&](int st) {   // load k-stage st into slot st%3 (tid 0 only)
        int s = st % 3;
        uint32_t mb = sb + 8 * s;
        mbar_expect_tx(mb, STAGE);
        const char* srcA = reinterpret_cast<const char*>(g_fused) +
                           ((size_t)(b * 16 + st) * 4096 + m0) * 128;
        const char* srcB = reinterpret_cast<const char*>(g_weff) +
                           ((size_t)(b * 16 + st) * 512 + n0) * 128;
        bulk_g2s(sb + SM_OFF + s * STAGE, srcA, A_BYTES, mb);
        bulk_g2s(sb + SM_OFF + s * STAGE + A_BYTES, srcB, B_BYTES, mb);
    };
    if (tid == 0) { issue(0); issue(1); issue(2); }

    float acc[4][4][4];
#pragma unroll
    for (int i = 0; i < 4; i++)
#pragma unroll
        for (int j = 0; j < 4; j++)
#pragma unroll
            for (int r = 0; r < 4; r++) acc[i][j][r] = 0.f;

#pragma unroll 1
    for (int kt = 0; kt < 16; ++kt) {
        int s = kt % 3;
        mbar_wait(sb + 8 * s, (kt / 3) & 1);

        const char* sA = smem + SM_OFF + s * STAGE;
        const char* sB = sA + A_BYTES;

#pragma unroll
        for (int ks = 0; ks < 4; ++ks) {
            // byte offsets in a 128B row; SW128 XORs 16B-chunk index with (row&7)=rq
            const int xb0 = (((2 * ks)     ^ rq) << 4) + (qq << 2);
            const int xb1 = (((2 * ks + 1) ^ rq) << 4) + (qq << 2);
            uint32_t a[4][4], bf[4][2];
#pragma unroll
            for (int i = 0; i < 4; i++) {
                int rb = (wm * 64 + i * 16 + rq) << 7;          // row * 128B
                a[i][0] = *reinterpret_cast<const uint32_t*>(sA + rb + xb0);
                a[i][1] = *reinterpret_cast<const uint32_t*>(sA + rb + 1024 + xb0);  // +8 rows
                a[i][2] = *reinterpret_cast<const uint32_t*>(sA + rb + xb1);
                a[i][3] = *reinterpret_cast<const uint32_t*>(sA + rb + 1024 + xb1);
            }
#pragma unroll
            for (int j = 0; j < 4; j++) {
                int rb = (wn * 32 + j * 8 + rq) << 7;
                bf[j][0] = *reinterpret_cast<const uint32_t*>(sB + rb + xb0);
                bf[j][1] = *reinterpret_cast<const uint32_t*>(sB + rb + xb1);
            }
#pragma unroll
            for (int i = 0; i < 4; i++)
#pragma unroll
                for (int j = 0; j < 4; j++) mma16(acc[i][j], a[i], bf[j]);
        }

        __syncthreads();                      // all warps done with slot s
        if (kt < 13 && tid == 0) issue(kt + 3);
    }

    // ---- epilogue: transpose through smem, fused BN + SiLU, coalesced STG ----
    float* eP = reinterpret_cast<float*>(smem + SM_OFF);   // [n 256][m 128], stride 132
#pragma unroll
    for (int i = 0; i < 4; i++) {
        int m = wm * 64 + i * 16 + rq;
#pragma unroll
        for (int j = 0; j < 4; j++) {
            int n = wn * 32 + j * 8 + 2 * qq;
            eP[n * 132 + m]           = acc[i][j][0];
            eP[(n + 1) * 132 + m]     = acc[i][j][1];
            eP[n * 132 + m + 8]       = acc[i][j][2];
            eP[(n + 1) * 132 + m + 8] = acc[i][j][3];
        }
    }
    __syncthreads();

#pragma unroll 1
    for (int idx = tid; idx < 256 * 32; idx += 512) {
        int row = idx >> 5;            // local output channel (uniform per warp)
        int seg = idx & 31;            // 4-float segment along m
        float4 v = *reinterpret_cast<const float4*>(eP + row * 132 + seg * 4);
        int oc = n0 + row;
        float s = g_bns[oc], t = g_bnb[oc];
        float z0 = v.x * s + t, z1 = v.y * s + t, z2 = v.z * s + t, z3 = v.w * s + t;
        float4 o4;
        o4.x = z0 / (1.0f + __expf(-z0));
        o4.y = z1 / (1.0f + __expf(-z1));
        o4.z = z2 / (1.0f + __expf(-z2));
        o4.w = z3 / (1.0f + __expf(-z3));
        *reinterpret_cast<float4*>(out + (((size_t)(b * 512 + oc)) << 12) + m0 + seg * 4) = o4;
    }
}

// ----------------------------------------------------------------------------
// Launch (4 kernels per call; g_sum starts zeroed: zero-init + k_weff tail)
// ----------------------------------------------------------------------------
extern "C" void kernel_launch(void* const* d_in, const int* in_sizes, int n_in,
                              void* d_out, int out_size) {
    const float* x      = (const float*)d_in[0];
    const float* w1     = (const float*)d_in[1];
    const float* w2     = (const float*)d_in[2];
    const float* conv_w = (const float*)d_in[3];
    const float* gamma  = (const float*)d_in[4];
    const float* beta   = (const float*)d_in[5];
    const float* mean   = (const float*)d_in[6];
    const float* var    = (const float*)d_in[7];
    float* out = (float*)d_out;
    (void)in_sizes; (void)n_in; (void)out_size;

    cudaFuncSetAttribute(k_gemm, cudaFuncAttributeMaxDynamicSharedMemorySize, SMEM_SZ);

    k_wavelet<<<dim3(128, 8, 8), 256>>>(x);
    k_mlp<<<9, 256>>>(w1, w2, gamma, beta, mean, var);
    k_weff<<<8192, 256>>>(conv_w);
    k_gemm<<<dim3(2, 32, 8), 512, SMEM_SZ>>>(out);
}

// round 7
// speedup vs baseline: 1.9504x; 1.3155x over previous
#include <cuda_runtime.h>
#include <cuda_fp16.h>
#include <cstdint>
#include <math.h>

#define DI __device__ __forceinline__

// ----------------------------------------------------------------------------
// Device scratch (no cudaMalloc allowed). K-major tiled, SW128-preswizzled:
//   g_fused: [b][kt=16][m=4096][64ch]  (128B rows, swizzled within 1KB blocks)
//   g_weff : [b][kt=16][o=512 ][64ch]
// ----------------------------------------------------------------------------
__device__ __half g_fused[8ull * 16ull * 4096ull * 64ull];
__device__ __half g_weff [8ull * 16ull * 512ull  * 64ull];
__device__ float  g_scale[8 * 1024];                 // per-(b,ch) gate (1.0 for LL)
__device__ float  g_sum  [8 * 768];                  // hf channel sums (zero-init; re-zeroed each call)
__device__ float  g_bns  [512];                      // folded BN scale
__device__ float  g_bnb  [512];                      // folded BN bias

// ----------------------------------------------------------------------------
// Helpers (baseline PTX only — no tcgen05 / no 'a'-gated features)
// ----------------------------------------------------------------------------
DI uint32_t sw128(uint32_t o) { return o ^ ((o >> 3) & 0x70u); }

DI uint32_t smem_u32(const void* p) {
    uint32_t a;
    asm("{ .reg .u64 t; cvta.to.shared.u64 t, %1; cvt.u32.u64 %0, t; }" : "=r"(a) : "l"(p));
    return a;
}
// global byte offset for (row, col2B) in a preswizzled [rows][64ch] tile
DI uint32_t tile_off(uint32_t row, uint32_t colbyte) {
    uint32_t off = row * 128u + colbyte;
    return (off & ~1023u) + sw128(off & 1023u);
}

DI void mbar_init(uint32_t mbar, uint32_t cnt) {
    asm volatile("mbarrier.init.shared.b64 [%0], %1;" :: "r"(mbar), "r"(cnt) : "memory");
}
DI void mbar_expect_tx(uint32_t mbar, uint32_t bytes) {
    asm volatile("mbarrier.arrive.expect_tx.shared.b64 _, [%0], %1;"
                 :: "r"(mbar), "r"(bytes) : "memory");
}
DI void mbar_wait(uint32_t mbar, uint32_t parity) {
    asm volatile(
        "{\n\t.reg .pred P1;\n\t"
        "LAB_WAIT_%=:\n\t"
        "mbarrier.try_wait.parity.acquire.cta.shared::cta.b64 P1, [%0], %1, 0x989680;\n\t"
        "@P1 bra.uni LAB_DONE_%=;\n\t"
        "bra.uni LAB_WAIT_%=;\n\t"
        "LAB_DONE_%=:\n\t}"
        :: "r"(mbar), "r"(parity) : "memory");
}
// 1-D bulk async copy global -> shared (sm_90 baseline; single thread issues)
DI void bulk_g2s(uint32_t dst, const void* src, uint32_t bytes, uint32_t mbar) {
    asm volatile(
        "cp.async.bulk.shared::cluster.global.mbarrier::complete_tx::bytes [%0], [%1], %2, [%3];"
        :: "r"(dst), "l"(__cvta_generic_to_global(src)), "r"(bytes), "r"(mbar) : "memory");
}

// ldmatrix x4: four 8x8 b16 matrices, lane-supplied row addresses
DI void ldsm4(uint32_t& r0, uint32_t& r1, uint32_t& r2, uint32_t& r3, uint32_t addr) {
    asm volatile("ldmatrix.sync.aligned.m8n8.x4.shared.b16 {%0,%1,%2,%3}, [%4];"
                 : "=r"(r0), "=r"(r1), "=r"(r2), "=r"(r3) : "r"(addr));
}

// fp16 HMMA with fp32 accumulate: D[16x8] += A[16x16] * B[16x8]
DI void mma16(float* c, const uint32_t* a, const uint32_t* b) {
    asm volatile(
        "mma.sync.aligned.m16n8k16.row.col.f32.f16.f16.f32 "
        "{%0,%1,%2,%3}, {%4,%5,%6,%7}, {%8,%9}, {%0,%1,%2,%3};"
        : "+f"(c[0]), "+f"(c[1]), "+f"(c[2]), "+f"(c[3])
        : "r"(a[0]), "r"(a[1]), "r"(a[2]), "r"(a[3]), "r"(b[0]), "r"(b[1]));
}

// ----------------------------------------------------------------------------
// K1: Haar DWT -> preswizzled K-major g_fused + hf channel sums
// grid (128 pos-tiles, 8 c-tiles, 8 b), 256 threads
// ----------------------------------------------------------------------------
__global__ __launch_bounds__(256) void k_wavelet(const float* __restrict__ x) {
    const int b = blockIdx.z, c0 = blockIdx.y * 32, p0 = blockIdx.x * 32;
    const int tid = threadIdx.x, lane = tid & 31, w = tid >> 5;

    __shared__ float sLL[32][33];
    __shared__ float sHF[3][32][33];

#pragma unroll
    for (int it = 0; it < 4; ++it) {
        int cc = it * 8 + w;
        int hw2 = p0 + lane;
        int h2 = hw2 >> 6, w2 = hw2 & 63;
        const float* xr = x + (((size_t)(b * 256 + c0 + cc) * 128 + 2 * h2) * 128 + 2 * w2);
        float2 t0 = *reinterpret_cast<const float2*>(xr);
        float2 t1 = *reinterpret_cast<const float2*>(xr + 128);
        sLL[cc][lane]    = 0.5f * (t0.x + t0.y + t1.x + t1.y);
        sHF[0][cc][lane] = 0.5f * (t0.x + t0.y - t1.x - t1.y);
        sHF[1][cc][lane] = 0.5f * (t0.x - t0.y + t1.x - t1.y);
        sHF[2][cc][lane] = 0.5f * (t0.x - t0.y - t1.x + t1.y);
    }
    __syncthreads();

    // hf channel sums: 96 rows (sbd, cc) x 32 pos, reduced by 4-thread groups
    {
        int q = tid & 3;
        {
            int rr = tid >> 2;                 // rows 0..63
            int sbd = rr >> 5, cc = rr & 31;
            float v = 0.f;
#pragma unroll
            for (int t = 0; t < 8; t++) v += sHF[sbd][cc][q * 8 + t];
            v += __shfl_down_sync(0xffffffffu, v, 1);
            v += __shfl_down_sync(0xffffffffu, v, 2);
            if (q == 0) atomicAdd(&g_sum[b * 768 + 3 * (c0 + cc) + sbd], v);
        }
        if (tid < 128) {
            int rr = 64 + (tid >> 2);          // rows 64..95
            int cc = rr & 31;                  // sbd == 2
            float v = 0.f;
#pragma unroll
            for (int t = 0; t < 8; t++) v += sHF[2][cc][q * 8 + t];
            v += __shfl_down_sync(0xffffffffu, v, 1);
            v += __shfl_down_sync(0xffffffffu, v, 2);
            if (q == 0) atomicAdd(&g_sum[b * 768 + 3 * (c0 + cc) + 2], v);
        }
    }

    // Write into K-major preswizzled layout (fp16)
#pragma unroll
    for (int it = 0; it < 16; ++it) {
        int wdx = it * 256 + tid;
        int pp = wdx >> 7, cl = wdx & 127;
        float v;
        int col;
        if (cl < 32) {
            v = sLL[cl][pp];
            col = c0 + cl;
        } else {
            int k = cl - 32;
            int cc = k / 3;
            int sb = k - 3 * cc;
            v = sHF[sb][cc][pp];
            col = 256 + 3 * c0 + k;
        }
        int m = p0 + pp;
        int kt = col >> 6, c6 = col & 63;
        char* base = reinterpret_cast<char*>(g_fused) + ((size_t)(b * 16 + kt) * 4096) * 128;
        *reinterpret_cast<__half*>(base + tile_off(m, c6 * 2)) = __float2half_rn(v);
    }
}

// ----------------------------------------------------------------------------
// K2: blocks 0..7 = per-batch MLP gate; block 8 = folded BN params
// ----------------------------------------------------------------------------
__global__ __launch_bounds__(256) void k_mlp(const float* __restrict__ w1, const float* __restrict__ w2,
                                             const float* __restrict__ gamma, const float* __restrict__ beta,
                                             const float* __restrict__ mean, const float* __restrict__ var) {
    int tid = threadIdx.x;
    if (blockIdx.x == 8) {
        for (int o = tid; o < 512; o += 256) {
            float s = gamma[o] * rsqrtf(var[o] + 1e-5f);
            g_bns[o] = s;
            g_bnb[o] = beta[o] - mean[o] * s;
        }
        return;
    }
    int b = blockIdx.x;
    __shared__ float s_mean[768];
    __shared__ float s_y1[48];
    for (int c = tid; c < 768; c += 256) s_mean[c] = g_sum[b * 768 + c] * (1.0f / 4096.0f);
    __syncthreads();
    int w = tid >> 5, lane = tid & 31;
#pragma unroll 1
    for (int i = 0; i < 6; i++) {
        int m = w + 8 * i;
        float acc = 0.f;
        for (int j = 0; j < 24; j++) {
            int c = lane + 32 * j;
            acc += s_mean[c] * w1[m * 768 + c];
        }
#pragma unroll
        for (int off = 16; off; off >>= 1) acc += __shfl_down_sync(0xffffffffu, acc, off);
        if (lane == 0) s_y1[m] = fmaxf(acc, 0.f);
    }
    __syncthreads();
    g_scale[b * 1024 + tid] = 1.0f;  // LL channels unscaled
    for (int c = tid; c < 768; c += 256) {
        float acc = 0.f;
#pragma unroll
        for (int m = 0; m < 48; m++) acc += s_y1[m] * w2[c * 48 + m];
        g_scale[b * 1024 + 256 + c] = 1.0f / (1.0f + expf(-acc));
    }
}

// ----------------------------------------------------------------------------
// K3: W_eff -> preswizzled K-major g_weff; also re-zero g_sum for next call
// ----------------------------------------------------------------------------
__global__ __launch_bounds__(256) void k_weff(const float* __restrict__ conv_w) {
    int idx = blockIdx.x * 256 + threadIdx.x;   // 2^21 half2 elems total
    int b   = idx >> 18;
    int r   = idx & 262143;
    int kt  = r >> 14;
    int r2  = r & 16383;
    int o   = r2 >> 5;
    int c2  = r2 & 31;                          // half2 within 64-col row
    int c   = kt * 64 + 2 * c2;
    float s0 = g_scale[b * 1024 + c];
    float s1 = g_scale[b * 1024 + c + 1];
    __half2 v = __floats2half2_rn(conv_w[o * 1024 + c] * s0, conv_w[o * 1024 + c + 1] * s1);
    char* base = reinterpret_cast<char*>(g_weff) + ((size_t)(b * 16 + kt) * 512) * 128;
    *reinterpret_cast<__half2*>(base + tile_off(o, c2 * 4)) = v;

    if (blockIdx.x == 0) {   // g_sum consumed by k_mlp already; zero for next call
        for (int i = threadIdx.x; i < 8 * 768; i += 256) g_sum[i] = 0.f;
    }
}

// ----------------------------------------------------------------------------
// K4: fp16 mma.sync GEMM, ldmatrix.x4 fragment feed, cp.async.bulk + mbarrier
//     4-stage pipeline. CTA tile 128M x 256N x 64K, 512 threads (16 warps,
//     2m x 8n, 64x32 warp tiles), preswizzled SW128 smem, smem-transposed
//     epilogue + BN + SiLU.  grid (2 ntile, 32 mtile, 8 b).
// ----------------------------------------------------------------------------
static constexpr int A_BYTES = 128 * 64 * 2;          // 16 KB
static constexpr int B_BYTES = 256 * 64 * 2;          // 32 KB
static constexpr int STAGE   = A_BYTES + B_BYTES;     // 48 KB
static constexpr int SM_OFF  = 1024;                  // mbars live below
static constexpr int SMEM_SZ = SM_OFF + 4 * STAGE;    // 197632

__global__ __launch_bounds__(512, 1) void k_gemm(float* __restrict__ out) {
    extern __shared__ __align__(1024) char smem[];
    const uint32_t sb = smem_u32(smem);
    const int tid = threadIdx.x, lane = tid & 31, wid = tid >> 5;
    const int wm = wid & 1, wn = wid >> 1;            // warp grid 2(m) x 8(n)
    const int rq = lane >> 2, qq = lane & 3;
    const int b = blockIdx.z, m0 = blockIdx.y * 128, n0 = blockIdx.x * 256;

    if (tid == 0) {
#pragma unroll
        for (int s = 0; s < 4; s++) mbar_init(sb + 8 * s, 1);
    }
    asm volatile("fence.proxy.async.shared::cta;" ::: "memory");
    __syncthreads();

    auto issue = [&](int st) {   // load k-stage st into slot st%4 (tid 0 only)
        int s = st & 3;
        uint32_t mb = sb + 8 * s;
        mbar_expect_tx(mb, STAGE);
        const char* srcA = reinterpret_cast<const char*>(g_fused) +
                           ((size_t)(b * 16 + st) * 4096 + m0) * 128;
        const char* srcB = reinterpret_cast<const char*>(g_weff) +
                           ((size_t)(b * 16 + st) * 512 + n0) * 128;
        bulk_g2s(sb + SM_OFF + s * STAGE, srcA, A_BYTES, mb);
        bulk_g2s(sb + SM_OFF + s * STAGE + A_BYTES, srcB, B_BYTES, mb);
    };
    if (tid == 0) { issue(0); issue(1); issue(2); issue(3); }

    float acc[4][4][4];
#pragma unroll
    for (int i = 0; i < 4; i++)
#pragma unroll
        for (int j = 0; j < 4; j++)
#pragma unroll
            for (int r = 0; r < 4; r++) acc[i][j][r] = 0.f;

    // ldmatrix lane addressing (SW128-aware), constant per thread:
    const int x7  = lane & 7;
    const int khA = lane >> 4;                                 // k-half for A
    const int khB = (lane >> 3) & 1;                           // k-half for B
    const uint32_t rowA_off = (uint32_t)(wm * 64 + (lane & 15)) << 7;
    const uint32_t rowB_off = (uint32_t)(wn * 32 + (lane & 7) + ((lane >> 4) << 3)) << 7;

#pragma unroll 1
    for (int kt = 0; kt < 16; ++kt) {
        int s = kt & 3;
        mbar_wait(sb + 8 * s, (kt >> 2) & 1);

        const uint32_t baseA = sb + SM_OFF + s * STAGE + rowA_off;
        const uint32_t baseB = sb + SM_OFF + s * STAGE + A_BYTES + rowB_off;

#pragma unroll
        for (int ks = 0; ks < 4; ++ks) {
            const uint32_t cA = (uint32_t)(((2 * ks + khA) ^ x7) << 4);
            const uint32_t cB = (uint32_t)(((2 * ks + khB) ^ x7) << 4);
            uint32_t a[4][4], bf[4][2];
#pragma unroll
            for (int i = 0; i < 4; i++)
                ldsm4(a[i][0], a[i][1], a[i][2], a[i][3], baseA + (i << 11) + cA);
            ldsm4(bf[0][0], bf[0][1], bf[1][0], bf[1][1], baseB + cB);
            ldsm4(bf[2][0], bf[2][1], bf[3][0], bf[3][1], baseB + (1 << 11) + cB);
#pragma unroll
            for (int i = 0; i < 4; i++)
#pragma unroll
                for (int j = 0; j < 4; j++) mma16(acc[i][j], a[i], bf[j]);
        }

        __syncthreads();                      // all warps done with slot s
        if (kt < 12 && tid == 0) issue(kt + 4);
    }

    // ---- epilogue: transpose through smem, fused BN + SiLU, coalesced STG ----
    float* eP = reinterpret_cast<float*>(smem + SM_OFF);   // [n 256][m 128], stride 132
#pragma unroll
    for (int i = 0; i < 4; i++) {
        int m = wm * 64 + i * 16 + rq;
#pragma unroll
        for (int j = 0; j < 4; j++) {
            int n = wn * 32 + j * 8 + 2 * qq;
            eP[n * 132 + m]           = acc[i][j][0];
            eP[(n + 1) * 132 + m]     = acc[i][j][1];
            eP[n * 132 + m + 8]       = acc[i][j][2];
            eP[(n + 1) * 132 + m + 8] = acc[i][j][3];
        }
    }
    __syncthreads();

#pragma unroll 1
    for (int idx = tid; idx < 256 * 32; idx += 512) {
        int row = idx >> 5;            // local output channel (uniform per warp)
        int seg = idx & 31;            // 4-float segment along m
        float4 v = *reinterpret_cast<const float4*>(eP + row * 132 + seg * 4);
        int oc = n0 + row;
        float s = g_bns[oc], t = g_bnb[oc];
        float z0 = v.x * s + t, z1 = v.y * s + t, z2 = v.z * s + t, z3 = v.w * s + t;
        float4 o4;
        o4.x = z0 / (1.0f + __expf(-z0));
        o4.y = z1 / (1.0f + __expf(-z1));
        o4.z = z2 / (1.0f + __expf(-z2));
        o4.w = z3 / (1.0f + __expf(-z3));
        *reinterpret_cast<float4*>(out + (((size_t)(b * 512 + oc)) << 12) + m0 + seg * 4) = o4;
    }
}

// ----------------------------------------------------------------------------
// Launch (4 kernels per call; g_sum starts zeroed: zero-init + k_weff tail)
// ----------------------------------------------------------------------------
extern "C" void kernel_launch(void* const* d_in, const int* in_sizes, int n_in,
                              void* d_out, int out_size) {
    const float* x      = (const float*)d_in[0];
    const float* w1     = (const float*)d_in[1];
    const float* w2     = (const float*)d_in[2];
    const float* conv_w = (const float*)d_in[3];
    const float* gamma  = (const float*)d_in[4];
    const float* beta   = (const float*)d_in[5];
    const float* mean   = (const float*)d_in[6];
    const float* var    = (const float*)d_in[7];
    float* out = (float*)d_out;
    (void)in_sizes; (void)n_in; (void)out_size;

    cudaFuncSetAttribute(k_gemm, cudaFuncAttributeMaxDynamicSharedMemorySize, SMEM_SZ);

    k_wavelet<<<dim3(128, 8, 8), 256>>>(x);
    k_mlp<<<9, 256>>>(w1, w2, gamma, beta, mean, var);
    k_weff<<<8192, 256>>>(conv_w);
    k_gemm<<<dim3(2, 32, 8), 512, SMEM_SZ>>>(out);
}

// round 8
// speedup vs baseline: 1.9658x; 1.0079x over previous
#include <cuda_runtime.h>
#include <cuda_fp16.h>
#include <cstdint>
#include <math.h>

#define DI __device__ __forceinline__

// ----------------------------------------------------------------------------
// Device scratch (no cudaMalloc allowed). K-major tiled, SW128-preswizzled:
//   g_fused: [b][kt=16][m=4096][64ch]  (128B rows, swizzled within 1KB blocks)
//   g_weff : [b][kt=16][o=512 ][64ch]
// ----------------------------------------------------------------------------
__device__ __half g_fused[8ull * 16ull * 4096ull * 64ull];
__device__ __half g_weff [8ull * 16ull * 512ull  * 64ull];
__device__ float  g_scale[8 * 1024];                 // per-(b,ch) gate (1.0 for LL)
__device__ float  g_sum  [8 * 768];                  // hf channel sums (zero-init; re-zeroed each call)
__device__ float  g_bns  [512];                      // folded BN scale
__device__ float  g_bnb  [512];                      // folded BN bias

// ----------------------------------------------------------------------------
// Helpers (baseline PTX only — no tcgen05 / no 'a'-gated features)
// ----------------------------------------------------------------------------
DI uint32_t sw128(uint32_t o) { return o ^ ((o >> 3) & 0x70u); }

DI uint32_t smem_u32(const void* p) {
    uint32_t a;
    asm("{ .reg .u64 t; cvta.to.shared.u64 t, %1; cvt.u32.u64 %0, t; }" : "=r"(a) : "l"(p));
    return a;
}
// global byte offset for (row, col2B) in a preswizzled [rows][64ch] tile
DI uint32_t tile_off(uint32_t row, uint32_t colbyte) {
    uint32_t off = row * 128u + colbyte;
    return (off & ~1023u) + sw128(off & 1023u);
}

DI void mbar_init(uint32_t mbar, uint32_t cnt) {
    asm volatile("mbarrier.init.shared.b64 [%0], %1;" :: "r"(mbar), "r"(cnt) : "memory");
}
DI void mbar_expect_tx(uint32_t mbar, uint32_t bytes) {
    asm volatile("mbarrier.arrive.expect_tx.shared.b64 _, [%0], %1;"
                 :: "r"(mbar), "r"(bytes) : "memory");
}
DI void mbar_wait(uint32_t mbar, uint32_t parity) {
    asm volatile(
        "{\n\t.reg .pred P1;\n\t"
        "LAB_WAIT_%=:\n\t"
        "mbarrier.try_wait.parity.acquire.cta.shared::cta.b64 P1, [%0], %1, 0x989680;\n\t"
        "@P1 bra.uni LAB_DONE_%=;\n\t"
        "bra.uni LAB_WAIT_%=;\n\t"
        "LAB_DONE_%=:\n\t}"
        :: "r"(mbar), "r"(parity) : "memory");
}
// 1-D bulk async copy global -> shared (sm_90 baseline; single thread issues)
DI void bulk_g2s(uint32_t dst, const void* src, uint32_t bytes, uint32_t mbar) {
    asm volatile(
        "cp.async.bulk.shared::cluster.global.mbarrier::complete_tx::bytes [%0], [%1], %2, [%3];"
        :: "r"(dst), "l"(__cvta_generic_to_global(src)), "r"(bytes), "r"(mbar) : "memory");
}

// ldmatrix x4: four 8x8 b16 matrices, lane-supplied row addresses
DI void ldsm4(uint32_t& r0, uint32_t& r1, uint32_t& r2, uint32_t& r3, uint32_t addr) {
    asm volatile("ldmatrix.sync.aligned.m8n8.x4.shared.b16 {%0,%1,%2,%3}, [%4];"
                 : "=r"(r0), "=r"(r1), "=r"(r2), "=r"(r3) : "r"(addr));
}

// fp16 HMMA with fp32 accumulate: D[16x8] += A[16x16] * B[16x8]
DI void mma16(float* c, const uint32_t* a, const uint32_t* b) {
    asm volatile(
        "mma.sync.aligned.m16n8k16.row.col.f32.f16.f16.f32 "
        "{%0,%1,%2,%3}, {%4,%5,%6,%7}, {%8,%9}, {%0,%1,%2,%3};"
        : "+f"(c[0]), "+f"(c[1]), "+f"(c[2]), "+f"(c[3])
        : "r"(a[0]), "r"(a[1]), "r"(a[2]), "r"(a[3]), "r"(b[0]), "r"(b[1]));
}

// ----------------------------------------------------------------------------
// K1: Haar DWT -> preswizzled K-major g_fused + hf channel sums
// grid (128 pos-tiles, 8 c-tiles, 8 b), 256 threads
// ----------------------------------------------------------------------------
__global__ __launch_bounds__(256) void k_wavelet(const float* __restrict__ x) {
    const int b = blockIdx.z, c0 = blockIdx.y * 32, p0 = blockIdx.x * 32;
    const int tid = threadIdx.x, lane = tid & 31, w = tid >> 5;

    __shared__ float sLL[32][33];
    __shared__ float sHF[3][32][33];

#pragma unroll
    for (int it = 0; it < 4; ++it) {
        int cc = it * 8 + w;
        int hw2 = p0 + lane;
        int h2 = hw2 >> 6, w2 = hw2 & 63;
        const float* xr = x + (((size_t)(b * 256 + c0 + cc) * 128 + 2 * h2) * 128 + 2 * w2);
        float2 t0 = *reinterpret_cast<const float2*>(xr);
        float2 t1 = *reinterpret_cast<const float2*>(xr + 128);
        sLL[cc][lane]    = 0.5f * (t0.x + t0.y + t1.x + t1.y);
        sHF[0][cc][lane] = 0.5f * (t0.x + t0.y - t1.x - t1.y);
        sHF[1][cc][lane] = 0.5f * (t0.x - t0.y + t1.x - t1.y);
        sHF[2][cc][lane] = 0.5f * (t0.x - t0.y - t1.x + t1.y);
    }
    __syncthreads();

    // hf channel sums: 96 rows (sbd, cc) x 32 pos, reduced by 4-thread groups
    {
        int q = tid & 3;
        {
            int rr = tid >> 2;                 // rows 0..63
            int sbd = rr >> 5, cc = rr & 31;
            float v = 0.f;
#pragma unroll
            for (int t = 0; t < 8; t++) v += sHF[sbd][cc][q * 8 + t];
            v += __shfl_down_sync(0xffffffffu, v, 1);
            v += __shfl_down_sync(0xffffffffu, v, 2);
            if (q == 0) atomicAdd(&g_sum[b * 768 + 3 * (c0 + cc) + sbd], v);
        }
        if (tid < 128) {
            int rr = 64 + (tid >> 2);          // rows 64..95
            int cc = rr & 31;                  // sbd == 2
            float v = 0.f;
#pragma unroll
            for (int t = 0; t < 8; t++) v += sHF[2][cc][q * 8 + t];
            v += __shfl_down_sync(0xffffffffu, v, 1);
            v += __shfl_down_sync(0xffffffffu, v, 2);
            if (q == 0) atomicAdd(&g_sum[b * 768 + 3 * (c0 + cc) + 2], v);
        }
    }

    // Write into K-major preswizzled layout as half2 pairs (cols never straddle
    // an LL/hf or 64-col kt boundary: c0 is a multiple of 32)
#pragma unroll
    for (int it = 0; it < 8; ++it) {
        int wdx = it * 256 + tid;              // 2048 half2 writes
        int pp = wdx >> 6, pc = wdx & 63;      // pos, pair-column
        int cl = 2 * pc;
        float v0, v1;
        int col;
        if (cl < 32) {
            v0 = sLL[cl][pp];
            v1 = sLL[cl + 1][pp];
            col = c0 + cl;
        } else {
            int k0 = cl - 32, k1 = k0 + 1;
            v0 = sHF[k0 % 3][k0 / 3][pp];
            v1 = sHF[k1 % 3][k1 / 3][pp];
            col = 256 + 3 * c0 + k0;
        }
        int m = p0 + pp;
        int kt = col >> 6, c6 = col & 63;
        char* base = reinterpret_cast<char*>(g_fused) + ((size_t)(b * 16 + kt) * 4096) * 128;
        *reinterpret_cast<__half2*>(base + tile_off(m, c6 * 2)) = __floats2half2_rn(v0, v1);
    }
}

// ----------------------------------------------------------------------------
// K2: blocks 0..7 = per-batch MLP gate; block 8 = folded BN params
// ----------------------------------------------------------------------------
__global__ __launch_bounds__(256) void k_mlp(const float* __restrict__ w1, const float* __restrict__ w2,
                                             const float* __restrict__ gamma, const float* __restrict__ beta,
                                             const float* __restrict__ mean, const float* __restrict__ var) {
    int tid = threadIdx.x;
    if (blockIdx.x == 8) {
        for (int o = tid; o < 512; o += 256) {
            float s = gamma[o] * rsqrtf(var[o] + 1e-5f);
            g_bns[o] = s;
            g_bnb[o] = beta[o] - mean[o] * s;
        }
        return;
    }
    int b = blockIdx.x;
    __shared__ float s_mean[768];
    __shared__ float s_y1[48];
    for (int c = tid; c < 768; c += 256) s_mean[c] = g_sum[b * 768 + c] * (1.0f / 4096.0f);
    __syncthreads();
    int w = tid >> 5, lane = tid & 31;
#pragma unroll 1
    for (int i = 0; i < 6; i++) {
        int m = w + 8 * i;
        float acc = 0.f;
        for (int j = 0; j < 24; j++) {
            int c = lane + 32 * j;
            acc += s_mean[c] * w1[m * 768 + c];
        }
#pragma unroll
        for (int off = 16; off; off >>= 1) acc += __shfl_down_sync(0xffffffffu, acc, off);
        if (lane == 0) s_y1[m] = fmaxf(acc, 0.f);
    }
    __syncthreads();
    g_scale[b * 1024 + tid] = 1.0f;  // LL channels unscaled
    for (int c = tid; c < 768; c += 256) {
        float acc = 0.f;
#pragma unroll
        for (int m = 0; m < 48; m++) acc += s_y1[m] * w2[c * 48 + m];
        g_scale[b * 1024 + 256 + c] = 1.0f / (1.0f + expf(-acc));
    }
}

// ----------------------------------------------------------------------------
// K3: W_eff -> preswizzled K-major g_weff; also re-zero g_sum for next call
// ----------------------------------------------------------------------------
__global__ __launch_bounds__(256) void k_weff(const float* __restrict__ conv_w) {
    int idx = blockIdx.x * 256 + threadIdx.x;   // 2^21 half2 elems total
    int b   = idx >> 18;
    int r   = idx & 262143;
    int kt  = r >> 14;
    int r2  = r & 16383;
    int o   = r2 >> 5;
    int c2  = r2 & 31;                          // half2 within 64-col row
    int c   = kt * 64 + 2 * c2;
    float s0 = g_scale[b * 1024 + c];
    float s1 = g_scale[b * 1024 + c + 1];
    __half2 v = __floats2half2_rn(conv_w[o * 1024 + c] * s0, conv_w[o * 1024 + c + 1] * s1);
    char* base = reinterpret_cast<char*>(g_weff) + ((size_t)(b * 16 + kt) * 512) * 128;
    *reinterpret_cast<__half2*>(base + tile_off(o, c2 * 4)) = v;

    if (blockIdx.x == 0) {   // g_sum consumed by k_mlp already; zero for next call
        for (int i = threadIdx.x; i < 8 * 768; i += 256) g_sum[i] = 0.f;
    }
}

// ----------------------------------------------------------------------------
// K4: fp16 mma.sync GEMM, ldmatrix.x4 feed, cp.async.bulk + mbarrier, 3-stage.
//     CTA tile 128M x 128N x 64K, 256 threads (8 warps, 2m x 4n, 64x32 warp
//     tiles), 2 CTAs/SM, preswizzled SW128 smem, smem-transposed epilogue +
//     BN + SiLU.  grid (4 ntile, 32 mtile, 8 b) = 1024 CTAs.
// ----------------------------------------------------------------------------
static constexpr int A_BYTES = 128 * 64 * 2;          // 16 KB
static constexpr int B_BYTES = 128 * 64 * 2;          // 16 KB
static constexpr int STAGE   = A_BYTES + B_BYTES;     // 32 KB
static constexpr int SM_OFF  = 1024;                  // mbars live below
static constexpr int SMEM_SZ = SM_OFF + 3 * STAGE;    // 99328

__global__ __launch_bounds__(256, 2) void k_gemm(float* __restrict__ out) {
    extern __shared__ __align__(1024) char smem[];
    const uint32_t sb = smem_u32(smem);
    const int tid = threadIdx.x, lane = tid & 31, wid = tid >> 5;
    const int wm = wid & 1, wn = wid >> 1;            // warp grid 2(m) x 4(n)
    const int rq = lane >> 2, qq = lane & 3;
    const int b = blockIdx.z, m0 = blockIdx.y * 128, n0 = blockIdx.x * 128;

    if (tid == 0) {
#pragma unroll
        for (int s = 0; s < 3; s++) mbar_init(sb + 8 * s, 1);
    }
    asm volatile("fence.proxy.async.shared::cta;" ::: "memory");
    __syncthreads();

    auto issue = [&](int st) {   // load k-stage st into slot st%3 (tid 0 only)
        int s = st % 3;
        uint32_t mb = sb + 8 * s;
        mbar_expect_tx(mb, STAGE);
        const char* srcA = reinterpret_cast<const char*>(g_fused) +
                           ((size_t)(b * 16 + st) * 4096 + m0) * 128;
        const char* srcB = reinterpret_cast<const char*>(g_weff) +
                           ((size_t)(b * 16 + st) * 512 + n0) * 128;
        bulk_g2s(sb + SM_OFF + s * STAGE, srcA, A_BYTES, mb);
        bulk_g2s(sb + SM_OFF + s * STAGE + A_BYTES, srcB, B_BYTES, mb);
    };
    if (tid == 0) { issue(0); issue(1); issue(2); }

    float acc[4][4][4];
#pragma unroll
    for (int i = 0; i < 4; i++)
#pragma unroll
        for (int j = 0; j < 4; j++)
#pragma unroll
            for (int r = 0; r < 4; r++) acc[i][j][r] = 0.f;

    // ldmatrix lane addressing (SW128-aware), constant per thread:
    const int x7  = lane & 7;
    const int khA = lane >> 4;                                 // k-half for A
    const int khB = (lane >> 3) & 1;                           // k-half for B
    const uint32_t rowA_off = (uint32_t)(wm * 64 + (lane & 15)) << 7;
    const uint32_t rowB_off = (uint32_t)(wn * 32 + (lane & 7) + ((lane >> 4) << 3)) << 7;

#pragma unroll 1
    for (int kt = 0; kt < 16; ++kt) {
        int s = kt % 3;
        mbar_wait(sb + 8 * s, (kt / 3) & 1);

        const uint32_t baseA = sb + SM_OFF + s * STAGE + rowA_off;
        const uint32_t baseB = sb + SM_OFF + s * STAGE + A_BYTES + rowB_off;

#pragma unroll
        for (int ks = 0; ks < 4; ++ks) {
            const uint32_t cA = (uint32_t)(((2 * ks + khA) ^ x7) << 4);
            const uint32_t cB = (uint32_t)(((2 * ks + khB) ^ x7) << 4);
            uint32_t a[4][4], bf[4][2];
#pragma unroll
            for (int i = 0; i < 4; i++)
                ldsm4(a[i][0], a[i][1], a[i][2], a[i][3], baseA + (i << 11) + cA);
            ldsm4(bf[0][0], bf[0][1], bf[1][0], bf[1][1], baseB + cB);
            ldsm4(bf[2][0], bf[2][1], bf[3][0], bf[3][1], baseB + (1 << 11) + cB);
#pragma unroll
            for (int i = 0; i < 4; i++)
#pragma unroll
                for (int j = 0; j < 4; j++) mma16(acc[i][j], a[i], bf[j]);
        }

        __syncthreads();                      // all warps done with slot s
        if (kt < 13 && tid == 0) issue(kt + 3);
    }

    // ---- epilogue: transpose through smem, fused BN + SiLU, coalesced STG ----
    float* eP = reinterpret_cast<float*>(smem + SM_OFF);   // [n 128][m 128], stride 132
#pragma unroll
    for (int i = 0; i < 4; i++) {
        int m = wm * 64 + i * 16 + rq;
#pragma unroll
        for (int j = 0; j < 4; j++) {
            int n = wn * 32 + j * 8 + 2 * qq;
            eP[n * 132 + m]           = acc[i][j][0];
            eP[(n + 1) * 132 + m]     = acc[i][j][1];
            eP[n * 132 + m + 8]       = acc[i][j][2];
            eP[(n + 1) * 132 + m + 8] = acc[i][j][3];
        }
    }
    __syncthreads();

#pragma unroll 1
    for (int idx = tid; idx < 128 * 32; idx += 256) {
        int row = idx >> 5;            // local output channel (uniform per warp)
        int seg = idx & 31;            // 4-float segment along m
        float4 v = *reinterpret_cast<const float4*>(eP + row * 132 + seg * 4);
        int oc = n0 + row;
        float s = g_bns[oc], t = g_bnb[oc];
        float z0 = v.x * s + t, z1 = v.y * s + t, z2 = v.z * s + t, z3 = v.w * s + t;
        float4 o4;
        o4.x = z0 / (1.0f + __expf(-z0));
        o4.y = z1 / (1.0f + __expf(-z1));
        o4.z = z2 / (1.0f + __expf(-z2));
        o4.w = z3 / (1.0f + __expf(-z3));
        *reinterpret_cast<float4*>(out + (((size_t)(b * 512 + oc)) << 12) + m0 + seg * 4) = o4;
    }
}

// ----------------------------------------------------------------------------
// Launch (4 kernels per call; g_sum starts zeroed: zero-init + k_weff tail)
// ----------------------------------------------------------------------------
extern "C" void kernel_launch(void* const* d_in, const int* in_sizes, int n_in,
                              void* d_out, int out_size) {
    const float* x      = (const float*)d_in[0];
    const float* w1     = (const float*)d_in[1];
    const float* w2     = (const float*)d_in[2];
    const float* conv_w = (const float*)d_in[3];
    const float* gamma  = (const float*)d_in[4];
    const float* beta   = (const float*)d_in[5];
    const float* mean   = (const float*)d_in[6];
    const float* var    = (const float*)d_in[7];
    float* out = (float*)d_out;
    (void)in_sizes; (void)n_in; (void)out_size;

    cudaFuncSetAttribute(k_gemm, cudaFuncAttributeMaxDynamicSharedMemorySize, SMEM_SZ);

    k_wavelet<<<dim3(128, 8, 8), 256>>>(x);
    k_mlp<<<9, 256>>>(w1, w2, gamma, beta, mean, var);
    k_weff<<<8192, 256>>>(conv_w);
    k_gemm<<<dim3(4, 32, 8), 256, SMEM_SZ>>>(out);
}

// round 10
// speedup vs baseline: 2.2697x; 1.1546x over previous
#include <cuda_runtime.h>
#include <cuda_fp16.h>
#include <cstdint>
#include <math.h>

#define DI __device__ __forceinline__

// ----------------------------------------------------------------------------
// Device scratch (no cudaMalloc allowed). K-major tiled, SW128-preswizzled:
//   g_fused: [b][kt=16][m=4096][64ch]  (128B rows, swizzled within 1KB blocks)
//   g_weff : [b][kt=16][o=512 ][64ch]
// ----------------------------------------------------------------------------
__device__ __half g_fused[8ull * 16ull * 4096ull * 64ull];
__device__ __half g_weff [8ull * 16ull * 512ull  * 64ull];
__device__ float  g_scale[8 * 1024];                 // per-(b,ch) gate (1.0 for LL)
__device__ float  g_sum  [8 * 768];                  // hf channel sums (zero-init; re-zeroed each call)
__device__ float  g_bns  [512];                      // folded BN scale
__device__ float  g_bnb  [512];                      // folded BN bias

// ----------------------------------------------------------------------------
// Helpers (baseline PTX only — no tcgen05 / no 'a'-gated features)
// ----------------------------------------------------------------------------
DI uint32_t sw128(uint32_t o) { return o ^ ((o >> 3) & 0x70u); }

DI uint32_t smem_u32(const void* p) {
    uint32_t a;
    asm("{ .reg .u64 t; cvta.to.shared.u64 t, %1; cvt.u32.u64 %0, t; }" : "=r"(a) : "l"(p));
    return a;
}
// global byte offset for (row, col2B) in a preswizzled [rows][64ch] tile
DI uint32_t tile_off(uint32_t row, uint32_t colbyte) {
    uint32_t off = row * 128u + colbyte;
    return (off & ~1023u) + sw128(off & 1023u);
}

DI void mbar_init(uint32_t mbar, uint32_t cnt) {
    asm volatile("mbarrier.init.shared.b64 [%0], %1;" :: "r"(mbar), "r"(cnt) : "memory");
}
DI void mbar_expect_tx(uint32_t mbar, uint32_t bytes) {
    asm volatile("mbarrier.arrive.expect_tx.shared.b64 _, [%0], %1;"
                 :: "r"(mbar), "r"(bytes) : "memory");
}
DI void mbar_arrive(uint32_t mbar) {
    asm volatile("mbarrier.arrive.shared.b64 _, [%0];" :: "r"(mbar) : "memory");
}
DI void mbar_wait(uint32_t mbar, uint32_t parity) {
    asm volatile(
        "{\n\t.reg .pred P1;\n\t"
        "LAB_WAIT_%=:\n\t"
        "mbarrier.try_wait.parity.acquire.cta.shared::cta.b64 P1, [%0], %1, 0x989680;\n\t"
        "@P1 bra.uni LAB_DONE_%=;\n\t"
        "bra.uni LAB_WAIT_%=;\n\t"
        "LAB_DONE_%=:\n\t}"
        :: "r"(mbar), "r"(parity) : "memory");
}
// 1-D bulk async copy global -> shared (sm_90 baseline; single thread issues)
DI void bulk_g2s(uint32_t dst, const void* src, uint32_t bytes, uint32_t mbar) {
    asm volatile(
        "cp.async.bulk.shared::cluster.global.mbarrier::complete_tx::bytes [%0], [%1], %2, [%3];"
        :: "r"(dst), "l"(__cvta_generic_to_global(src)), "r"(bytes), "r"(mbar) : "memory");
}

// ldmatrix x4: four 8x8 b16 matrices, lane-supplied row addresses
DI void ldsm4(uint32_t& r0, uint32_t& r1, uint32_t& r2, uint32_t& r3, uint32_t addr) {
    asm volatile("ldmatrix.sync.aligned.m8n8.x4.shared.b16 {%0,%1,%2,%3}, [%4];"
                 : "=r"(r0), "=r"(r1), "=r"(r2), "=r"(r3) : "r"(addr));
}

// fp16 HMMA with fp32 accumulate: D[16x8] += A[16x16] * B[16x8]
DI void mma16(float* c, const uint32_t* a, const uint32_t* b) {
    asm volatile(
        "mma.sync.aligned.m16n8k16.row.col.f32.f16.f16.f32 "
        "{%0,%1,%2,%3}, {%4,%5,%6,%7}, {%8,%9}, {%0,%1,%2,%3};"
        : "+f"(c[0]), "+f"(c[1]), "+f"(c[2]), "+f"(c[3])
        : "r"(a[0]), "r"(a[1]), "r"(a[2]), "r"(a[3]), "r"(b[0]), "r"(b[1]));
}

// ----------------------------------------------------------------------------
// K1: Haar DWT -> preswizzled K-major g_fused + hf channel sums
// grid (128 pos-tiles, 8 c-tiles, 8 b), 256 threads
// ----------------------------------------------------------------------------
__global__ __launch_bounds__(256) void k_wavelet(const float* __restrict__ x) {
    const int b = blockIdx.z, c0 = blockIdx.y * 32, p0 = blockIdx.x * 32;
    const int tid = threadIdx.x, lane = tid & 31, w = tid >> 5;

    __shared__ float sLL[32][33];
    __shared__ float sHF[3][32][33];

#pragma unroll
    for (int it = 0; it < 4; ++it) {
        int cc = it * 8 + w;
        int hw2 = p0 + lane;
        int h2 = hw2 >> 6, w2 = hw2 & 63;
        const float* xr = x + (((size_t)(b * 256 + c0 + cc) * 128 + 2 * h2) * 128 + 2 * w2);
        float2 t0 = *reinterpret_cast<const float2*>(xr);
        float2 t1 = *reinterpret_cast<const float2*>(xr + 128);
        sLL[cc][lane]    = 0.5f * (t0.x + t0.y + t1.x + t1.y);
        sHF[0][cc][lane] = 0.5f * (t0.x + t0.y - t1.x - t1.y);
        sHF[1][cc][lane] = 0.5f * (t0.x - t0.y + t1.x - t1.y);
        sHF[2][cc][lane] = 0.5f * (t0.x - t0.y - t1.x + t1.y);
    }
    __syncthreads();

    // hf channel sums: 96 rows (sbd, cc) x 32 pos, reduced by 4-thread groups
    {
        int q = tid & 3;
        {
            int rr = tid >> 2;                 // rows 0..63
            int sbd = rr >> 5, cc = rr & 31;
            float v = 0.f;
#pragma unroll
            for (int t = 0; t < 8; t++) v += sHF[sbd][cc][q * 8 + t];
            v += __shfl_down_sync(0xffffffffu, v, 1);
            v += __shfl_down_sync(0xffffffffu, v, 2);
            if (q == 0) atomicAdd(&g_sum[b * 768 + 3 * (c0 + cc) + sbd], v);
        }
        if (tid < 128) {
            int rr = 64 + (tid >> 2);          // rows 64..95
            int cc = rr & 31;                  // sbd == 2
            float v = 0.f;
#pragma unroll
            for (int t = 0; t < 8; t++) v += sHF[2][cc][q * 8 + t];
            v += __shfl_down_sync(0xffffffffu, v, 1);
            v += __shfl_down_sync(0xffffffffu, v, 2);
            if (q == 0) atomicAdd(&g_sum[b * 768 + 3 * (c0 + cc) + 2], v);
        }
    }

    // Write as 16B chunks (8 consecutive channels). Each chunk stays inside one
    // 64-col kt tile (chunk col-base is 8-aligned; LL base c0 is 32-aligned and
    // hf base 256+3*c0 is 8-aligned), and 16B alignment survives the SW128
    // swizzle (which permutes whole 16B chunks). 512 chunks, 2 per thread.
#pragma unroll
    for (int it = 0; it < 2; ++it) {
        int wdx = it * 256 + tid;
        int pp = wdx >> 4, ci = wdx & 15;      // pos, chunk index
        int cl = ci * 8;
        __half2 h[4];
        int col;
        if (cl < 32) {
#pragma unroll
            for (int t = 0; t < 4; t++)
                h[t] = __floats2half2_rn(sLL[cl + 2 * t][pp], sLL[cl + 2 * t + 1][pp]);
            col = c0 + cl;
        } else {
            int k0 = cl - 32;
            float v[8];
#pragma unroll
            for (int t = 0; t < 8; t++) {
                int k = k0 + t;
                v[t] = sHF[k % 3][k / 3][pp];
            }
#pragma unroll
            for (int t = 0; t < 4; t++) h[t] = __floats2half2_rn(v[2 * t], v[2 * t + 1]);
            col = 256 + 3 * c0 + k0;
        }
        int m = p0 + pp;
        int kt = col >> 6, c6 = col & 63;
        char* base = reinterpret_cast<char*>(g_fused) + ((size_t)(b * 16 + kt) * 4096) * 128;
        const uint32_t* hw = reinterpret_cast<const uint32_t*>(h);
        uint4 pack;
        pack.x = hw[0];
        pack.y = hw[1];
        pack.z = hw[2];
        pack.w = hw[3];
        *reinterpret_cast<uint4*>(base + tile_off(m, c6 * 2)) = pack;
    }
}

// ----------------------------------------------------------------------------
// K2: blocks 0..7 = per-batch MLP gate; block 8 = folded BN params
// ----------------------------------------------------------------------------
__global__ __launch_bounds__(256) void k_mlp(const float* __restrict__ w1, const float* __restrict__ w2,
                                             const float* __restrict__ gamma, const float* __restrict__ beta,
                                             const float* __restrict__ mean, const float* __restrict__ var) {
    int tid = threadIdx.x;
    if (blockIdx.x == 8) {
        for (int o = tid; o < 512; o += 256) {
            float s = gamma[o] * rsqrtf(var[o] + 1e-5f);
            g_bns[o] = s;
            g_bnb[o] = beta[o] - mean[o] * s;
        }
        return;
    }
    int b = blockIdx.x;
    __shared__ float s_mean[768];
    __shared__ float s_y1[48];
    for (int c = tid; c < 768; c += 256) s_mean[c] = g_sum[b * 768 + c] * (1.0f / 4096.0f);
    __syncthreads();
    int w = tid >> 5, lane = tid & 31;
#pragma unroll 1
    for (int i = 0; i < 6; i++) {
        int m = w + 8 * i;
        float acc = 0.f;
        for (int j = 0; j < 24; j++) {
            int c = lane + 32 * j;
            acc += s_mean[c] * w1[m * 768 + c];
        }
#pragma unroll
        for (int off = 16; off; off >>= 1) acc += __shfl_down_sync(0xffffffffu, acc, off);
        if (lane == 0) s_y1[m] = fmaxf(acc, 0.f);
    }
    __syncthreads();
    g_scale[b * 1024 + tid] = 1.0f;  // LL channels unscaled
    for (int c = tid; c < 768; c += 256) {
        float acc = 0.f;
#pragma unroll
        for (int m = 0; m < 48; m++) acc += s_y1[m] * w2[c * 48 + m];
        g_scale[b * 1024 + 256 + c] = 1.0f / (1.0f + expf(-acc));
    }
}

// ----------------------------------------------------------------------------
// K3: W_eff -> preswizzled K-major g_weff; also re-zero g_sum for next call
// ----------------------------------------------------------------------------
__global__ __launch_bounds__(256) void k_weff(const float* __restrict__ conv_w) {
    int idx = blockIdx.x * 256 + threadIdx.x;   // 2^21 half2 elems total
    int b   = idx >> 18;
    int r   = idx & 262143;
    int kt  = r >> 14;
    int r2  = r & 16383;
    int o   = r2 >> 5;
    int c2  = r2 & 31;                          // half2 within 64-col row
    int c   = kt * 64 + 2 * c2;
    float s0 = g_scale[b * 1024 + c];
    float s1 = g_scale[b * 1024 + c + 1];
    __half2 v = __floats2half2_rn(conv_w[o * 1024 + c] * s0, conv_w[o * 1024 + c + 1] * s1);
    char* base = reinterpret_cast<char*>(g_weff) + ((size_t)(b * 16 + kt) * 512) * 128;
    *reinterpret_cast<__half2*>(base + tile_off(o, c2 * 4)) = v;

    if (blockIdx.x == 0) {   // g_sum consumed by k_mlp already; zero for next call
        for (int i = threadIdx.x; i < 8 * 768; i += 256) g_sum[i] = 0.f;
    }
}

// ----------------------------------------------------------------------------
// K4: fp16 mma.sync GEMM, ldmatrix.x4 feed, cp.async.bulk, free-running
//     producer/consumer mbarrier pipeline (no per-kt __syncthreads).
//     CTA tile 128M x 128N x 64K, 256 threads (8 warps, 2m x 4n), 2 CTAs/SM,
//     preswizzled SW128 smem, smem-transposed epilogue + BN + SiLU.
//     grid (4 ntile, 32 mtile, 8 b) = 1024 CTAs.
// ----------------------------------------------------------------------------
static constexpr int A_BYTES = 128 * 64 * 2;          // 16 KB
static constexpr int B_BYTES = 128 * 64 * 2;          // 16 KB
static constexpr int STAGE   = A_BYTES + B_BYTES;     // 32 KB
static constexpr int SM_OFF  = 1024;                  // mbars live below
static constexpr int SMEM_SZ = SM_OFF + 3 * STAGE;    // 99328

__global__ __launch_bounds__(256, 2) void k_gemm(float* __restrict__ out) {
    extern __shared__ __align__(1024) char smem[];
    const uint32_t sb = smem_u32(smem);
    const int tid = threadIdx.x, lane = tid & 31, wid = tid >> 5;
    const int wm = wid & 1, wn = wid >> 1;            // warp grid 2(m) x 4(n)
    const int rq = lane >> 2, qq = lane & 3;
    const int b = blockIdx.z, m0 = blockIdx.y * 128, n0 = blockIdx.x * 128;

    if (tid == 0) {
#pragma unroll
        for (int s = 0; s < 3; s++) {
            mbar_init(sb + 8 * s, 1);        // full[s]
            mbar_init(sb + 32 + 8 * s, 256); // empty[s]
        }
    }
    asm volatile("fence.proxy.async.shared::cta;" ::: "memory");
    __syncthreads();

    auto issue = [&](int st) {   // load k-stage st into slot st%3 (tid 0 only)
        int s = st % 3;
        uint32_t mb = sb + 8 * s;
        mbar_expect_tx(mb, STAGE);
        const char* srcA = reinterpret_cast<const char*>(g_fused) +
                           ((size_t)(b * 16 + st) * 4096 + m0) * 128;
        const char* srcB = reinterpret_cast<const char*>(g_weff) +
                           ((size_t)(b * 16 + st) * 512 + n0) * 128;
        bulk_g2s(sb + SM_OFF + s * STAGE, srcA, A_BYTES, mb);
        bulk_g2s(sb + SM_OFF + s * STAGE + A_BYTES, srcB, B_BYTES, mb);
    };
    if (tid == 0) { issue(0); issue(1); issue(2); }

    float acc[4][4][4];
#pragma unroll
    for (int i = 0; i < 4; i++)
#pragma unroll
        for (int j = 0; j < 4; j++)
#pragma unroll
            for (int r = 0; r < 4; r++) acc[i][j][r] = 0.f;

    // ldmatrix lane addressing (SW128-aware), constant per thread:
    const int x7  = lane & 7;
    const int khA = lane >> 4;                                 // k-half for A
    const int khB = (lane >> 3) & 1;                           // k-half for B
    const uint32_t rowA_off = (uint32_t)(wm * 64 + (lane & 15)) << 7;
    const uint32_t rowB_off = (uint32_t)(wn * 32 + (lane & 7) + ((lane >> 4) << 3)) << 7;

#pragma unroll 1
    for (int kt = 0; kt < 16; ++kt) {
        int s = kt % 3;
        mbar_wait(sb + 8 * s, (kt / 3) & 1);              // full[s]

        const uint32_t baseA = sb + SM_OFF + s * STAGE + rowA_off;
        const uint32_t baseB = sb + SM_OFF + s * STAGE + A_BYTES + rowB_off;

#pragma unroll
        for (int ks = 0; ks < 4; ++ks) {
            const uint32_t cA = (uint32_t)(((2 * ks + khA) ^ x7) << 4);
            const uint32_t cB = (uint32_t)(((2 * ks + khB) ^ x7) << 4);
            uint32_t a[4][4], bf[4][2];
#pragma unroll
            for (int i = 0; i < 4; i++)
                ldsm4(a[i][0], a[i][1], a[i][2], a[i][3], baseA + (i << 11) + cA);
            ldsm4(bf[0][0], bf[0][1], bf[1][0], bf[1][1], baseB + cB);
            ldsm4(bf[2][0], bf[2][1], bf[3][0], bf[3][1], baseB + (1 << 11) + cB);
#pragma unroll
            for (int i = 0; i < 4; i++)
#pragma unroll
                for (int j = 0; j < 4; j++) mma16(acc[i][j], a[i], bf[j]);
        }

        mbar_arrive(sb + 32 + 8 * s);                     // done reading slot s
        if (kt < 13 && tid == 0) {
            mbar_wait(sb + 32 + 8 * s, (kt / 3) & 1);     // all consumed slot s
            issue(kt + 3);
        }
    }
    __syncthreads();   // all warps out of the mainloop before smem reuse

    // ---- epilogue: transpose through smem, fused BN + SiLU, coalesced STG ----
    float* eP = reinterpret_cast<float*>(smem + SM_OFF);   // [n 128][m 128], stride 132
#pragma unroll
    for (int i = 0; i < 4; i++) {
        int m = wm * 64 + i * 16 + rq;
#pragma unroll
        for (int j = 0; j < 4; j++) {
            int n = wn * 32 + j * 8 + 2 * qq;
            eP[n * 132 + m]           = acc[i][j][0];
            eP[(n + 1) * 132 + m]     = acc[i][j][1];
            eP[n * 132 + m + 8]       = acc[i][j][2];
            eP[(n + 1) * 132 + m + 8] = acc[i][j][3];
        }
    }
    __syncthreads();

#pragma unroll 1
    for (int idx = tid; idx < 128 * 32; idx += 256) {
        int row = idx >> 5;            // local output channel (uniform per warp)
        int seg = idx & 31;            // 4-float segment along m
        float4 v = *reinterpret_cast<const float4*>(eP + row * 132 + seg * 4);
        int oc = n0 + row;
        float s = g_bns[oc], t = g_bnb[oc];
        float z0 = v.x * s + t, z1 = v.y * s + t, z2 = v.z * s + t, z3 = v.w * s + t;
        float4 o4;
        o4.x = z0 / (1.0f + __expf(-z0));
        o4.y = z1 / (1.0f + __expf(-z1));
        o4.z = z2 / (1.0f + __expf(-z2));
        o4.w = z3 / (1.0f + __expf(-z3));
        *reinterpret_cast<float4*>(out + (((size_t)(b * 512 + oc)) << 12) + m0 + seg * 4) = o4;
    }
}

// ----------------------------------------------------------------------------
// Launch (4 kernels per call; g_sum starts zeroed: zero-init + k_weff tail)
// ----------------------------------------------------------------------------
extern "C" void kernel_launch(void* const* d_in, const int* in_sizes, int n_in,
                              void* d_out, int out_size) {
    const float* x      = (const float*)d_in[0];
    const float* w1     = (const float*)d_in[1];
    const float* w2     = (const float*)d_in[2];
    const float* conv_w = (const float*)d_in[3];
    const float* gamma  = (const float*)d_in[4];
    const float* beta   = (const float*)d_in[5];
    const float* mean   = (const float*)d_in[6];
    const float* var    = (const float*)d_in[7];
    float* out = (float*)d_out;
    (void)in_sizes; (void)n_in; (void)out_size;

    cudaFuncSetAttribute(k_gemm, cudaFuncAttributeMaxDynamicSharedMemorySize, SMEM_SZ);

    k_wavelet<<<dim3(128, 8, 8), 256>>>(x);
    k_mlp<<<9, 256>>>(w1, w2, gamma, beta, mean, var);
    k_weff<<<8192, 256>>>(conv_w);
    k_gemm<<<dim3(4, 32, 8), 256, SMEM_SZ>>>(out);
}

// round 12
// speedup vs baseline: 2.2728x; 1.0014x over previous
#include <cuda_runtime.h>
#include <cuda_fp16.h>
#include <cstdint>
#include <math.h>

#define DI __device__ __forceinline__

// ----------------------------------------------------------------------------
// Device scratch (no cudaMalloc allowed). K-major tiled, SW128-preswizzled:
//   g_fused: [b][kt=16][m=4096][64ch]  (128B rows, swizzled within 1KB blocks)
//   g_wh   : [kt=16][o=512][64ch]      (shared fp16 weights, unscaled)
// ----------------------------------------------------------------------------
__device__ __half g_fused[8ull * 16ull * 4096ull * 64ull];
__device__ __half g_wh   [16ull * 512ull * 64ull];
__device__ __half g_scale_h[8 * 1024];               // per-(b,ch) gate fp16 (1.0 for LL)
__device__ float  g_sum  [8 * 768];                  // hf channel sums (zero-init; re-zeroed each call)
__device__ float  g_bns  [512];                      // folded BN scale
__device__ float  g_bnb  [512];                      // folded BN bias

// ----------------------------------------------------------------------------
// Helpers (baseline PTX only — no tcgen05 / no 'a'-gated features)
// ----------------------------------------------------------------------------
DI uint32_t sw128(uint32_t o) { return o ^ ((o >> 3) & 0x70u); }

DI uint32_t smem_u32(const void* p) {
    uint32_t a;
    asm("{ .reg .u64 t; cvta.to.shared.u64 t, %1; cvt.u32.u64 %0, t; }" : "=r"(a) : "l"(p));
    return a;
}
// global byte offset for (row, col2B) in a preswizzled [rows][64ch] tile
DI uint32_t tile_off(uint32_t row, uint32_t colbyte) {
    uint32_t off = row * 128u + colbyte;
    return (off & ~1023u) + sw128(off & 1023u);
}

DI void mbar_init(uint32_t mbar, uint32_t cnt) {
    asm volatile("mbarrier.init.shared.b64 [%0], %1;" :: "r"(mbar), "r"(cnt) : "memory");
}
DI void mbar_expect_tx(uint32_t mbar, uint32_t bytes) {
    asm volatile("mbarrier.arrive.expect_tx.shared.b64 _, [%0], %1;"
                 :: "r"(mbar), "r"(bytes) : "memory");
}
DI void mbar_arrive(uint32_t mbar) {
    asm volatile("mbarrier.arrive.shared.b64 _, [%0];" :: "r"(mbar) : "memory");
}
DI void mbar_wait(uint32_t mbar, uint32_t parity) {
    asm volatile(
        "{\n\t.reg .pred P1;\n\t"
        "LAB_WAIT_%=:\n\t"
        "mbarrier.try_wait.parity.acquire.cta.shared::cta.b64 P1, [%0], %1, 0x989680;\n\t"
        "@P1 bra.uni LAB_DONE_%=;\n\t"
        "bra.uni LAB_WAIT_%=;\n\t"
        "LAB_DONE_%=:\n\t}"
        :: "r"(mbar), "r"(parity) : "memory");
}
// 1-D bulk async copy global -> shared (sm_90 baseline; single thread issues)
DI void bulk_g2s(uint32_t dst, const void* src, uint32_t bytes, uint32_t mbar) {
    asm volatile(
        "cp.async.bulk.shared::cluster.global.mbarrier::complete_tx::bytes [%0], [%1], %2, [%3];"
        :: "r"(dst), "l"(__cvta_generic_to_global(src)), "r"(bytes), "r"(mbar) : "memory");
}

// ldmatrix x4: four 8x8 b16 matrices, lane-supplied row addresses
DI void ldsm4(uint32_t& r0, uint32_t& r1, uint32_t& r2, uint32_t& r3, uint32_t addr) {
    asm volatile("ldmatrix.sync.aligned.m8n8.x4.shared.b16 {%0,%1,%2,%3}, [%4];"
                 : "=r"(r0), "=r"(r1), "=r"(r2), "=r"(r3) : "r"(addr));
}

// fp16 HMMA with fp32 accumulate: D[16x8] += A[16x16] * B[16x8]
DI void mma16(float* c, const uint32_t* a, const uint32_t* b) {
    asm volatile(
        "mma.sync.aligned.m16n8k16.row.col.f32.f16.f16.f32 "
        "{%0,%1,%2,%3}, {%4,%5,%6,%7}, {%8,%9}, {%0,%1,%2,%3};"
        : "+f"(c[0]), "+f"(c[1]), "+f"(c[2]), "+f"(c[3])
        : "r"(a[0]), "r"(a[1]), "r"(a[2]), "r"(a[3]), "r"(b[0]), "r"(b[1]));
}

DI uint32_t h2mul(uint32_t a, uint32_t s) {
    uint32_t d;
    asm("mul.rn.f16x2 %0, %1, %2;" : "=r"(d) : "r"(a), "r"(s));
    return d;
}

// ----------------------------------------------------------------------------
// K1: Haar DWT -> preswizzled K-major g_fused + hf channel sums
// grid (128 pos-tiles, 8 c-tiles, 8 b), 256 threads
// ----------------------------------------------------------------------------
__global__ __launch_bounds__(256) void k_wavelet(const float* __restrict__ x) {
    const int b = blockIdx.z, c0 = blockIdx.y * 32, p0 = blockIdx.x * 32;
    const int tid = threadIdx.x, lane = tid & 31, w = tid >> 5;

    __shared__ float sLL[32][33];
    __shared__ float sHF[3][32][33];

#pragma unroll
    for (int it = 0; it < 4; ++it) {
        int cc = it * 8 + w;
        int hw2 = p0 + lane;
        int h2 = hw2 >> 6, w2 = hw2 & 63;
        const float* xr = x + (((size_t)(b * 256 + c0 + cc) * 128 + 2 * h2) * 128 + 2 * w2);
        float2 t0 = *reinterpret_cast<const float2*>(xr);
        float2 t1 = *reinterpret_cast<const float2*>(xr + 128);
        sLL[cc][lane]    = 0.5f * (t0.x + t0.y + t1.x + t1.y);
        sHF[0][cc][lane] = 0.5f * (t0.x + t0.y - t1.x - t1.y);
        sHF[1][cc][lane] = 0.5f * (t0.x - t0.y + t1.x - t1.y);
        sHF[2][cc][lane] = 0.5f * (t0.x - t0.y - t1.x + t1.y);
    }
    __syncthreads();

    // hf channel sums: 96 rows (sbd, cc) x 32 pos, reduced by 4-thread groups
    {
        int q = tid & 3;
        {
            int rr = tid >> 2;                 // rows 0..63
            int sbd = rr >> 5, cc = rr & 31;
            float v = 0.f;
#pragma unroll
            for (int t = 0; t < 8; t++) v += sHF[sbd][cc][q * 8 + t];
            v += __shfl_down_sync(0xffffffffu, v, 1);
            v += __shfl_down_sync(0xffffffffu, v, 2);
            if (q == 0) atomicAdd(&g_sum[b * 768 + 3 * (c0 + cc) + sbd], v);
        }
        if (tid < 128) {
            int rr = 64 + (tid >> 2);          // rows 64..95
            int cc = rr & 31;                  // sbd == 2
            float v = 0.f;
#pragma unroll
            for (int t = 0; t < 8; t++) v += sHF[2][cc][q * 8 + t];
            v += __shfl_down_sync(0xffffffffu, v, 1);
            v += __shfl_down_sync(0xffffffffu, v, 2);
            if (q == 0) atomicAdd(&g_sum[b * 768 + 3 * (c0 + cc) + 2], v);
        }
    }

    // Write as 16B chunks (8 consecutive channels); chunks stay inside one
    // 64-col kt tile and 16B alignment survives SW128 (permutes whole chunks).
#pragma unroll
    for (int it = 0; it < 2; ++it) {
        int wdx = it * 256 + tid;
        int pp = wdx >> 4, ci = wdx & 15;      // pos, chunk index
        int cl = ci * 8;
        __half2 h[4];
        int col;
        if (cl < 32) {
#pragma unroll
            for (int t = 0; t < 4; t++)
                h[t] = __floats2half2_rn(sLL[cl + 2 * t][pp], sLL[cl + 2 * t + 1][pp]);
            col = c0 + cl;
        } else {
            int k0 = cl - 32;
            float v[8];
#pragma unroll
            for (int t = 0; t < 8; t++) {
                int k = k0 + t;
                v[t] = sHF[k % 3][k / 3][pp];
            }
#pragma unroll
            for (int t = 0; t < 4; t++) h[t] = __floats2half2_rn(v[2 * t], v[2 * t + 1]);
            col = 256 + 3 * c0 + k0;
        }
        int m = p0 + pp;
        int kt = col >> 6, c6 = col & 63;
        char* base = reinterpret_cast<char*>(g_fused) + ((size_t)(b * 16 + kt) * 4096) * 128;
        const uint32_t* hw = reinterpret_cast<const uint32_t*>(h);
        uint4 pack;
        pack.x = hw[0];
        pack.y = hw[1];
        pack.z = hw[2];
        pack.w = hw[3];
        *reinterpret_cast<uint4*>(base + tile_off(m, c6 * 2)) = pack;
    }
}

// ----------------------------------------------------------------------------
// K2: blocks 0..7 = per-batch MLP gate (fp16) + g_sum re-zero;
//     block 8 = folded BN params;
//     blocks 9..1032 = conv_w -> preswizzled fp16 g_wh (batch-independent)
// ----------------------------------------------------------------------------
__global__ __launch_bounds__(256) void k_mlp(const float* __restrict__ w1, const float* __restrict__ w2,
                                             const float* __restrict__ gamma, const float* __restrict__ beta,
                                             const float* __restrict__ mean, const float* __restrict__ var,
                                             const float* __restrict__ conv_w) {
    int tid = threadIdx.x;
    int bx = blockIdx.x;
    if (bx >= 9) {                              // weight conversion: 262144 half2
        int u  = (bx - 9) * 256 + tid;
        int kt = u >> 14;                       // 16384 half2 per kt tile (512 rows x 32)
        int r2 = u & 16383;
        int o  = r2 >> 5;
        int c2 = r2 & 31;
        int c  = kt * 64 + 2 * c2;
        __half2 v = __floats2half2_rn(conv_w[o * 1024 + c], conv_w[o * 1024 + c + 1]);
        char* base = reinterpret_cast<char*>(g_wh) + (size_t)kt * 512 * 128;
        *reinterpret_cast<__half2*>(base + tile_off(o, c2 * 4)) = v;
        return;
    }
    if (bx == 8) {
        for (int o = tid; o < 512; o += 256) {
            float s = gamma[o] * rsqrtf(var[o] + 1e-5f);
            g_bns[o] = s;
            g_bnb[o] = beta[o] - mean[o] * s;
        }
        return;
    }
    int b = bx;
    __shared__ float s_mean[768];
    __shared__ float s_y1[48];
    for (int c = tid; c < 768; c += 256) s_mean[c] = g_sum[b * 768 + c] * (1.0f / 4096.0f);
    __syncthreads();
    int w = tid >> 5, lane = tid & 31;
#pragma unroll 1
    for (int i = 0; i < 6; i++) {
        int m = w + 8 * i;
        float acc = 0.f;
        for (int j = 0; j < 24; j++) {
            int c = lane + 32 * j;
            acc += s_mean[c] * w1[m * 768 + c];
        }
#pragma unroll
        for (int off = 16; off; off >>= 1) acc += __shfl_down_sync(0xffffffffu, acc, off);
        if (lane == 0) s_y1[m] = fmaxf(acc, 0.f);
    }
    __syncthreads();
    g_scale_h[b * 1024 + tid] = __float2half(1.0f);   // LL channels unscaled
    for (int c = tid; c < 768; c += 256) {
        float acc = 0.f;
#pragma unroll
        for (int m = 0; m < 48; m++) acc += s_y1[m] * w2[c * 48 + m];
        g_scale_h[b * 1024 + 256 + c] = __float2half_rn(1.0f / (1.0f + expf(-acc)));
    }
    // g_sum consumed above; zero this batch's slice for the next call
    for (int i = tid; i < 768; i += 256) g_sum[b * 768 + i] = 0.f;
}

// ----------------------------------------------------------------------------
// K4: fp16 mma.sync GEMM, gate folded into B fragments (mul.f16x2), shared
//     L2-resident weights, ldmatrix.x4 feed, cp.async.bulk free-running
//     pipeline. CTA tile 128M x 128N x 64K, 256 threads (8 warps, 2m x 4n),
//     2 CTAs/SM, smem-transposed epilogue + BN + SiLU. grid (4,32,8).
// ----------------------------------------------------------------------------
static constexpr int A_BYTES = 128 * 64 * 2;          // 16 KB
static constexpr int B_BYTES = 128 * 64 * 2;          // 16 KB
static constexpr int STAGE   = A_BYTES + B_BYTES;     // 32 KB
static constexpr int SC_OFF  = 64;                    // gate scales (2 KB) after mbars
static constexpr int SM_OFF  = 4096;                  // stage buffers
static constexpr int SMEM_SZ = SM_OFF + 3 * STAGE;    // 102400

__global__ __launch_bounds__(256, 2) void k_gemm(float* __restrict__ out) {
    extern __shared__ __align__(1024) char smem[];
    const uint32_t sb = smem_u32(smem);
    const int tid = threadIdx.x, lane = tid & 31, wid = tid >> 5;
    const int wm = wid & 1, wn = wid >> 1;            // warp grid 2(m) x 4(n)
    const int rq = lane >> 2, qq = lane & 3;
    const int b = blockIdx.z, m0 = blockIdx.y * 128, n0 = blockIdx.x * 128;

    if (tid == 0) {
#pragma unroll
        for (int s = 0; s < 3; s++) {
            mbar_init(sb + 8 * s, 1);        // full[s]
            mbar_init(sb + 32 + 8 * s, 8);   // empty[s]: one arrive per warp
        }
    }
    // preload gate scales for this batch: 1024 half = 512 u32
    {
        const uint32_t* src = reinterpret_cast<const uint32_t*>(g_scale_h + b * 1024);
        uint32_t* dst = reinterpret_cast<uint32_t*>(smem + SC_OFF);
        dst[tid] = src[tid];
        dst[tid + 256] = src[tid + 256];
    }
    asm volatile("fence.proxy.async.shared::cta;" ::: "memory");
    __syncthreads();

    auto issue = [&](int st) {   // load k-stage st into slot st%3 (tid 0 only)
        int s = st % 3;
        uint32_t mb = sb + 8 * s;
        mbar_expect_tx(mb, STAGE);
        const char* srcA = reinterpret_cast<const char*>(g_fused) +
                           ((size_t)(b * 16 + st) * 4096 + m0) * 128;
        const char* srcB = reinterpret_cast<const char*>(g_wh) +
                           ((size_t)st * 512 + n0) * 128;
        bulk_g2s(sb + SM_OFF + s * STAGE, srcA, A_BYTES, mb);
        bulk_g2s(sb + SM_OFF + s * STAGE + A_BYTES, srcB, B_BYTES, mb);
    };
    if (tid == 0) { issue(0); issue(1); issue(2); }

    float acc[4][4][4];
#pragma unroll
    for (int i = 0; i < 4; i++)
#pragma unroll
        for (int j = 0; j < 4; j++)
#pragma unroll
            for (int r = 0; r < 4; r++) acc[i][j][r] = 0.f;

    // ldmatrix lane addressing (SW128-aware), constant per thread:
    const int x7  = lane & 7;
    const int khA = lane >> 4;                                 // k-half for A
    const int khB = (lane >> 3) & 1;                           // k-half for B
    const uint32_t rowA_off = (uint32_t)(wm * 64 + (lane & 15)) << 7;
    const uint32_t rowB_off = (uint32_t)(wn * 32 + (lane & 7) + ((lane >> 4) << 3)) << 7;
    const char* scp = smem + SC_OFF + qq * 4;                  // per-thread scale base

#pragma unroll 1
    for (int kt = 0; kt < 16; ++kt) {
        int s = kt % 3;
        mbar_wait(sb + 8 * s, (kt / 3) & 1);              // full[s]

        const uint32_t baseA = sb + SM_OFF + s * STAGE + rowA_off;
        const uint32_t baseB = sb + SM_OFF + s * STAGE + A_BYTES + rowB_off;
        const char* sck = scp + kt * 128;

#pragma unroll
        for (int ks = 0; ks < 4; ++ks) {
            const uint32_t cA = (uint32_t)(((2 * ks + khA) ^ x7) << 4);
            const uint32_t cB = (uint32_t)(((2 * ks + khB) ^ x7) << 4);
            uint32_t a[4][4], bf[4][2];
#pragma unroll
            for (int i = 0; i < 4; i++)
                ldsm4(a[i][0], a[i][1], a[i][2], a[i][3], baseA + (i << 11) + cA);
            ldsm4(bf[0][0], bf[0][1], bf[1][0], bf[1][1], baseB + cB);
            ldsm4(bf[2][0], bf[2][1], bf[3][0], bf[3][1], baseB + (1 << 11) + cB);
            // gate: k = kt*64 + ks*16 + g*8 + 2qq + {0,1}; reg index g selects +16B
            uint32_t s0 = *reinterpret_cast<const uint32_t*>(sck + ks * 32);
            uint32_t s1 = *reinterpret_cast<const uint32_t*>(sck + ks * 32 + 16);
#pragma unroll
            for (int j = 0; j < 4; j++) {
                bf[j][0] = h2mul(bf[j][0], s0);
                bf[j][1] = h2mul(bf[j][1], s1);
            }
#pragma unroll
            for (int i = 0; i < 4; i++)
#pragma unroll
                for (int j = 0; j < 4; j++) mma16(acc[i][j], a[i], bf[j]);
        }

        if (lane == 0) mbar_arrive(sb + 32 + 8 * s);      // warp done with slot s
        if (kt < 13 && tid == 0) {
            mbar_wait(sb + 32 + 8 * s, (kt / 3) & 1);     // all warps consumed slot s
            issue(kt + 3);
        }
    }
    __syncthreads();   // all warps out of the mainloop before smem reuse

    // ---- epilogue: transpose through smem, fused BN + SiLU, coalesced STG ----
    float* eP = reinterpret_cast<float*>(smem + SM_OFF);   // [n 128][m 128], stride 132
#pragma unroll
    for (int i = 0; i < 4; i++) {
        int m = wm * 64 + i * 16 + rq;
#pragma unroll
        for (int j = 0; j < 4; j++) {
            int n = wn * 32 + j * 8 + 2 * qq;
            eP[n * 132 + m]           = acc[i][j][0];
            eP[(n + 1) * 132 + m]     = acc[i][j][1];
            eP[n * 132 + m + 8]       = acc[i][j][2];
            eP[(n + 1) * 132 + m + 8] = acc[i][j][3];
        }
    }
    __syncthreads();

#pragma unroll 1
    for (int idx = tid; idx < 128 * 32; idx += 256) {
        int row = idx >> 5;            // local output channel (uniform per warp)
        int seg = idx & 31;            // 4-float segment along m
        float4 v = *reinterpret_cast<const float4*>(eP + row * 132 + seg * 4);
        int oc = n0 + row;
        float s = g_bns[oc], t = g_bnb[oc];
        float z0 = v.x * s + t, z1 = v.y * s + t, z2 = v.z * s + t, z3 = v.w * s + t;
        float4 o4;
        o4.x = z0 / (1.0f + __expf(-z0));
        o4.y = z1 / (1.0f + __expf(-z1));
        o4.z = z2 / (1.0f + __expf(-z2));
        o4.w = z3 / (1.0f + __expf(-z3));
        *reinterpret_cast<float4*>(out + (((size_t)(b * 512 + oc)) << 12) + m0 + seg * 4) = o4;
    }
}

// ----------------------------------------------------------------------------
// Launch (3 kernels per call; g_sum starts zeroed: zero-init + k_mlp tail)
// ----------------------------------------------------------------------------
extern "C" void kernel_launch(void* const* d_in, const int* in_sizes, int n_in,
                              void* d_out, int out_size) {
    const float* x      = (const float*)d_in[0];
    const float* w1     = (const float*)d_in[1];
    const float* w2     = (const float*)d_in[2];
    const float* conv_w = (const float*)d_in[3];
    const float* gamma  = (const float*)d_in[4];
    const float* beta   = (const float*)d_in[5];
    const float* mean   = (const float*)d_in[6];
    const float* var    = (const float*)d_in[7];
    float* out = (float*)d_out;
    (void)in_sizes; (void)n_in; (void)out_size;

    cudaFuncSetAttribute(k_gemm, cudaFuncAttributeMaxDynamicSharedMemorySize, SMEM_SZ);

    k_wavelet<<<dim3(128, 8, 8), 256>>>(x);
    k_mlp<<<1033, 256>>>(w1, w2, gamma, beta, mean, var, conv_w);
    k_gemm<<<dim3(4, 32, 8), 256, SMEM_SZ>>>(out);
}

// round 13
// speedup vs baseline: 2.4291x; 1.0688x over previous
#include <cuda_runtime.h>
#include <cuda_fp16.h>
#include <cstdint>
#include <math.h>

#define DI __device__ __forceinline__

// ----------------------------------------------------------------------------
// Device scratch (no cudaMalloc allowed). K-major tiled, SW128-preswizzled:
//   g_fused: [b][kt=16][m=4096][64ch]  (128B rows, swizzled within 1KB blocks)
//   g_wh   : [kt=16][o=512][64ch]      (shared fp16 weights, unscaled)
// ----------------------------------------------------------------------------
__device__ __half g_fused[8ull * 16ull * 4096ull * 64ull];
__device__ __half g_wh   [16ull * 512ull * 64ull];
__device__ __half g_scale_h[8 * 1024];               // per-(b,ch) gate fp16 (1.0 for LL)
__device__ float  g_sum  [8 * 768];                  // hf channel sums (zero-init; re-zeroed each call)
__device__ float  g_bns  [512];                      // folded BN scale
__device__ float  g_bnb  [512];                      // folded BN bias

// ----------------------------------------------------------------------------
// Helpers (baseline PTX only — no tcgen05 / no 'a'-gated features)
// ----------------------------------------------------------------------------
DI uint32_t sw128(uint32_t o) { return o ^ ((o >> 3) & 0x70u); }

DI uint32_t smem_u32(const void* p) {
    uint32_t a;
    asm("{ .reg .u64 t; cvta.to.shared.u64 t, %1; cvt.u32.u64 %0, t; }" : "=r"(a) : "l"(p));
    return a;
}
// global byte offset for (row, col2B) in a preswizzled [rows][64ch] tile
DI uint32_t tile_off(uint32_t row, uint32_t colbyte) {
    uint32_t off = row * 128u + colbyte;
    return (off & ~1023u) + sw128(off & 1023u);
}

DI void mbar_init(uint32_t mbar, uint32_t cnt) {
    asm volatile("mbarrier.init.shared.b64 [%0], %1;" :: "r"(mbar), "r"(cnt) : "memory");
}
DI void mbar_expect_tx(uint32_t mbar, uint32_t bytes) {
    asm volatile("mbarrier.arrive.expect_tx.shared.b64 _, [%0], %1;"
                 :: "r"(mbar), "r"(bytes) : "memory");
}
DI void mbar_arrive(uint32_t mbar) {
    asm volatile("mbarrier.arrive.shared.b64 _, [%0];" :: "r"(mbar) : "memory");
}
DI void mbar_wait(uint32_t mbar, uint32_t parity) {
    asm volatile(
        "{\n\t.reg .pred P1;\n\t"
        "LAB_WAIT_%=:\n\t"
        "mbarrier.try_wait.parity.acquire.cta.shared::cta.b64 P1, [%0], %1, 0x989680;\n\t"
        "@P1 bra.uni LAB_DONE_%=;\n\t"
        "bra.uni LAB_WAIT_%=;\n\t"
        "LAB_DONE_%=:\n\t}"
        :: "r"(mbar), "r"(parity) : "memory");
}
// 1-D bulk async copy global -> shared (sm_90 baseline; single thread issues)
DI void bulk_g2s(uint32_t dst, const void* src, uint32_t bytes, uint32_t mbar) {
    asm volatile(
        "cp.async.bulk.shared::cluster.global.mbarrier::complete_tx::bytes [%0], [%1], %2, [%3];"
        :: "r"(dst), "l"(__cvta_generic_to_global(src)), "r"(bytes), "r"(mbar) : "memory");
}

// ldmatrix x4: four 8x8 b16 matrices, lane-supplied row addresses
DI void ldsm4(uint32_t& r0, uint32_t& r1, uint32_t& r2, uint32_t& r3, uint32_t addr) {
    asm volatile("ldmatrix.sync.aligned.m8n8.x4.shared.b16 {%0,%1,%2,%3}, [%4];"
                 : "=r"(r0), "=r"(r1), "=r"(r2), "=r"(r3) : "r"(addr));
}

// fp16 HMMA with fp32 accumulate: D[16x8] += A[16x16] * B[16x8]
DI void mma16(float* c, const uint32_t* a, const uint32_t* b) {
    asm volatile(
        "mma.sync.aligned.m16n8k16.row.col.f32.f16.f16.f32 "
        "{%0,%1,%2,%3}, {%4,%5,%6,%7}, {%8,%9}, {%0,%1,%2,%3};"
        : "+f"(c[0]), "+f"(c[1]), "+f"(c[2]), "+f"(c[3])
        : "r"(a[0]), "r"(a[1]), "r"(a[2]), "r"(a[3]), "r"(b[0]), "r"(b[1]));
}

DI uint32_t h2mul(uint32_t a, uint32_t s) {
    uint32_t d;
    asm("mul.rn.f16x2 %0, %1, %2;" : "=r"(d) : "r"(a), "r"(s));
    return d;
}

// ----------------------------------------------------------------------------
// K1: Haar DWT -> preswizzled K-major g_fused + hf channel sums.
//     blockIdx.z==8 blocks instead convert conv_w -> preswizzled fp16 g_wh.
// grid (128 pos-tiles, 8 c-tiles, 9), 256 threads
// smem layout: sW[128][33]; element (r, pp) at column (pp + 5*(r>>3)) & 31.
//   rows 0..31  = LL channel cc = r
//   rows 32..127 = hf: r = 32 + 3*cc + subband
// ----------------------------------------------------------------------------
__global__ __launch_bounds__(256) void k_wavelet(const float* __restrict__ x,
                                                 const float* __restrict__ conv_w) {
    const int tid = threadIdx.x;
    if (blockIdx.z == 8) {      // weight conversion: 262144 half2 over 1024 blocks
        int u  = (blockIdx.y * 128 + blockIdx.x) * 256 + tid;
        int kt = u >> 14;                       // 16384 half2 per kt tile (512 rows x 32)
        int r2 = u & 16383;
        int o  = r2 >> 5;
        int c2 = r2 & 31;
        int c  = kt * 64 + 2 * c2;
        __half2 v = __floats2half2_rn(conv_w[o * 1024 + c], conv_w[o * 1024 + c + 1]);
        char* base = reinterpret_cast<char*>(g_wh) + (size_t)kt * 512 * 128;
        *reinterpret_cast<__half2*>(base + tile_off(o, c2 * 4)) = v;
        return;
    }

    const int b = blockIdx.z, c0 = blockIdx.y * 32, p0 = blockIdx.x * 32;
    const int lane = tid & 31, w = tid >> 5;

    __shared__ float sW[128][33];

#pragma unroll
    for (int it = 0; it < 4; ++it) {
        int cc = it * 8 + w;
        int hw2 = p0 + lane;
        int h2 = hw2 >> 6, w2 = hw2 & 63;
        const float* xr = x + (((size_t)(b * 256 + c0 + cc) * 128 + 2 * h2) * 128 + 2 * w2);
        float2 t0 = *reinterpret_cast<const float2*>(xr);
        float2 t1 = *reinterpret_cast<const float2*>(xr + 128);
        float ll = 0.5f * (t0.x + t0.y + t1.x + t1.y);
        float lh = 0.5f * (t0.x + t0.y - t1.x - t1.y);
        float hl = 0.5f * (t0.x - t0.y + t1.x - t1.y);
        float hh = 0.5f * (t0.x - t0.y - t1.x + t1.y);
        sW[cc][(lane + 5 * it) & 31] = ll;                       // cc>>3 == it
        int rh = 32 + 3 * cc;
        sW[rh][(lane + 5 * (rh >> 3)) & 31] = lh;
        sW[rh + 1][(lane + 5 * ((rh + 1) >> 3)) & 31] = hl;
        sW[rh + 2][(lane + 5 * ((rh + 2) >> 3)) & 31] = hh;
    }
    __syncthreads();

    // hf channel sums: rows 32..127 = channel 3*c0 + rr, reduced by 4-thread groups
    {
        int q = tid & 3;
        {
            int rr = tid >> 2;                 // rr 0..63 -> rows 32..95
            int row = 32 + rr;
            int sh = 5 * (row >> 3);
            float v = 0.f;
#pragma unroll
            for (int t = 0; t < 8; t++) v += sW[row][(q * 8 + t + sh) & 31];
            v += __shfl_down_sync(0xffffffffu, v, 1);
            v += __shfl_down_sync(0xffffffffu, v, 2);
            if (q == 0) atomicAdd(&g_sum[b * 768 + 3 * c0 + rr], v);
        }
        if (tid < 128) {
            int rr = 64 + (tid >> 2);          // rows 96..127
            int row = 32 + rr;
            int sh = 5 * (row >> 3);
            float v = 0.f;
#pragma unroll
            for (int t = 0; t < 8; t++) v += sW[row][(q * 8 + t + sh) & 31];
            v += __shfl_down_sync(0xffffffffu, v, 1);
            v += __shfl_down_sync(0xffffffffu, v, 2);
            if (q == 0) atomicAdd(&g_sum[b * 768 + 3 * c0 + rr], v);
        }
    }

    // Write as 16B chunks (8 consecutive output channels). Rows are uniform:
    // chunk ci covers rows 8ci..8ci+7 of sW for both LL (cl<32) and hf regions.
#pragma unroll
    for (int it = 0; it < 2; ++it) {
        int wdx = it * 256 + tid;
        int pp = wdx >> 4, ci = wdx & 15;      // pos, chunk index
        int cl = ci * 8;
        int co = (pp + 5 * ci) & 31;           // stored column for rows 8ci..8ci+7
        float v[8];
#pragma unroll
        for (int t = 0; t < 8; t++) v[t] = sW[cl + t][co];
        __half2 h[4];
#pragma unroll
        for (int t = 0; t < 4; t++) h[t] = __floats2half2_rn(v[2 * t], v[2 * t + 1]);
        int col = (cl < 32) ? (c0 + cl) : (256 + 3 * c0 + (cl - 32));
        int m = p0 + pp;
        int kt = col >> 6, c6 = col & 63;
        char* base = reinterpret_cast<char*>(g_fused) + ((size_t)(b * 16 + kt) * 4096) * 128;
        const uint32_t* hw = reinterpret_cast<const uint32_t*>(h);
        uint4 pack;
        pack.x = hw[0];
        pack.y = hw[1];
        pack.z = hw[2];
        pack.w = hw[3];
        *reinterpret_cast<uint4*>(base + tile_off(m, c6 * 2)) = pack;
    }
}

// ----------------------------------------------------------------------------
// K2: blocks 0..7 = per-batch MLP gate (fp16) + g_sum re-zero;
//     block 8 = folded BN params
// ----------------------------------------------------------------------------
__global__ __launch_bounds__(256) void k_mlp(const float* __restrict__ w1, const float* __restrict__ w2,
                                             const float* __restrict__ gamma, const float* __restrict__ beta,
                                             const float* __restrict__ mean, const float* __restrict__ var) {
    int tid = threadIdx.x;
    int bx = blockIdx.x;
    if (bx == 8) {
        for (int o = tid; o < 512; o += 256) {
            float s = gamma[o] * rsqrtf(var[o] + 1e-5f);
            g_bns[o] = s;
            g_bnb[o] = beta[o] - mean[o] * s;
        }
        return;
    }
    int b = bx;
    __shared__ float s_mean[768];
    __shared__ float s_y1[48];
    for (int c = tid; c < 768; c += 256) s_mean[c] = g_sum[b * 768 + c] * (1.0f / 4096.0f);
    __syncthreads();
    int w = tid >> 5, lane = tid & 31;
#pragma unroll 1
    for (int i = 0; i < 6; i++) {
        int m = w + 8 * i;
        float acc = 0.f;
        for (int j = 0; j < 24; j++) {
            int c = lane + 32 * j;
            acc += s_mean[c] * w1[m * 768 + c];
        }
#pragma unroll
        for (int off = 16; off; off >>= 1) acc += __shfl_down_sync(0xffffffffu, acc, off);
        if (lane == 0) s_y1[m] = fmaxf(acc, 0.f);
    }
    __syncthreads();
    g_scale_h[b * 1024 + tid] = __float2half(1.0f);   // LL channels unscaled
    for (int c = tid; c < 768; c += 256) {
        float acc = 0.f;
#pragma unroll
        for (int m = 0; m < 48; m++) acc += s_y1[m] * w2[c * 48 + m];
        g_scale_h[b * 1024 + 256 + c] = __float2half_rn(1.0f / (1.0f + expf(-acc)));
    }
    // g_sum consumed above; zero this batch's slice for the next call
    for (int i = tid; i < 768; i += 256) g_sum[b * 768 + i] = 0.f;
}

// ----------------------------------------------------------------------------
// K4: fp16 mma.sync GEMM, gate folded into B fragments (double-buffered across
//     ks so h2mul hides under mma), shared L2-resident weights, ldmatrix.x4,
//     cp.async.bulk free-running pipeline. CTA tile 128M x 128N x 64K,
//     256 threads (8 warps, 2m x 4n), 2 CTAs/SM, smem-transposed epilogue +
//     BN + SiLU. grid (4,32,8).
// ----------------------------------------------------------------------------
static constexpr int A_BYTES = 128 * 64 * 2;          // 16 KB
static constexpr int B_BYTES = 128 * 64 * 2;          // 16 KB
static constexpr int STAGE   = A_BYTES + B_BYTES;     // 32 KB
static constexpr int SC_OFF  = 64;                    // gate scales (2 KB) after mbars
static constexpr int SM_OFF  = 4096;                  // stage buffers
static constexpr int SMEM_SZ = SM_OFF + 3 * STAGE;    // 102400

__global__ __launch_bounds__(256, 2) void k_gemm(float* __restrict__ out) {
    extern __shared__ __align__(1024) char smem[];
    const uint32_t sb = smem_u32(smem);
    const int tid = threadIdx.x, lane = tid & 31, wid = tid >> 5;
    const int wm = wid & 1, wn = wid >> 1;            // warp grid 2(m) x 4(n)
    const int rq = lane >> 2, qq = lane & 3;
    const int b = blockIdx.z, m0 = blockIdx.y * 128, n0 = blockIdx.x * 128;

    if (tid == 0) {
#pragma unroll
        for (int s = 0; s < 3; s++) {
            mbar_init(sb + 8 * s, 1);        // full[s]
            mbar_init(sb + 32 + 8 * s, 8);   // empty[s]: one arrive per warp
        }
    }
    // preload gate scales for this batch: 1024 half = 512 u32
    {
        const uint32_t* src = reinterpret_cast<const uint32_t*>(g_scale_h + b * 1024);
        uint32_t* dst = reinterpret_cast<uint32_t*>(smem + SC_OFF);
        dst[tid] = src[tid];
        dst[tid + 256] = src[tid + 256];
    }
    asm volatile("fence.proxy.async.shared::cta;" ::: "memory");
    __syncthreads();

    auto issue = [&](int st) {   // load k-stage st into slot st%3 (tid 0 only)
        int s = st % 3;
        uint32_t mb = sb + 8 * s;
        mbar_expect_tx(mb, STAGE);
        const char* srcA = reinterpret_cast<const char*>(g_fused) +
                           ((size_t)(b * 16 + st) * 4096 + m0) * 128;
        const char* srcB = reinterpret_cast<const char*>(g_wh) +
                           ((size_t)st * 512 + n0) * 128;
        bulk_g2s(sb + SM_OFF + s * STAGE, srcA, A_BYTES, mb);
        bulk_g2s(sb + SM_OFF + s * STAGE + A_BYTES, srcB, B_BYTES, mb);
    };
    if (tid == 0) { issue(0); issue(1); issue(2); }

    float acc[4][4][4];
#pragma unroll
    for (int i = 0; i < 4; i++)
#pragma unroll
        for (int j = 0; j < 4; j++)
#pragma unroll
            for (int r = 0; r < 4; r++) acc[i][j][r] = 0.f;

    // ldmatrix lane addressing (SW128-aware), constant per thread:
    const int x7  = lane & 7;
    const int khA = lane >> 4;                                 // k-half for A
    const int khB = (lane >> 3) & 1;                           // k-half for B
    const uint32_t rowA_off = (uint32_t)(wm * 64 + (lane & 15)) << 7;
    const uint32_t rowB_off = (uint32_t)(wn * 32 + (lane & 7) + ((lane >> 4) << 3)) << 7;
    const char* scp = smem + SC_OFF + qq * 4;                  // per-thread scale base

#pragma unroll 1
    for (int kt = 0; kt < 16; ++kt) {
        int s = kt % 3;
        mbar_wait(sb + 8 * s, (kt / 3) & 1);              // full[s]

        const uint32_t baseA = sb + SM_OFF + s * STAGE + rowA_off;
        const uint32_t baseB = sb + SM_OFF + s * STAGE + A_BYTES + rowB_off;
        const char* sck = scp + kt * 128;

        // double-buffered, gate-scaled B fragments
        uint32_t bf0[4][2], bf1[4][2];
        auto loadB = [&](int ks, uint32_t (&bf)[4][2]) {
            const uint32_t cB = (uint32_t)(((2 * ks + khB) ^ x7) << 4);
            ldsm4(bf[0][0], bf[0][1], bf[1][0], bf[1][1], baseB + cB);
            ldsm4(bf[2][0], bf[2][1], bf[3][0], bf[3][1], baseB + (1 << 11) + cB);
            // gate: k = kt*64 + ks*16 + g*8 + 2qq + {0,1}; reg index g selects +16B
            uint32_t s0 = *reinterpret_cast<const uint32_t*>(sck + ks * 32);
            uint32_t s1 = *reinterpret_cast<const uint32_t*>(sck + ks * 32 + 16);
#pragma unroll
            for (int j = 0; j < 4; j++) {
                bf[j][0] = h2mul(bf[j][0], s0);
                bf[j][1] = h2mul(bf[j][1], s1);
            }
        };
        loadB(0, bf0);

#pragma unroll
        for (int ks = 0; ks < 4; ++ks) {
            const uint32_t cA = (uint32_t)(((2 * ks + khA) ^ x7) << 4);
            uint32_t a[4][4];
#pragma unroll
            for (int i = 0; i < 4; i++)
                ldsm4(a[i][0], a[i][1], a[i][2], a[i][3], baseA + (i << 11) + cA);
            if (ks < 3) loadB(ks + 1, (ks & 1) ? bf0 : bf1);
            uint32_t (&cur)[4][2] = (ks & 1) ? bf1 : bf0;
#pragma unroll
            for (int i = 0; i < 4; i++)
#pragma unroll
                for (int j = 0; j < 4; j++) mma16(acc[i][j], a[i], cur[j]);
        }

        if (lane == 0) mbar_arrive(sb + 32 + 8 * s);      // warp done with slot s
        if (kt < 13 && tid == 0) {
            mbar_wait(sb + 32 + 8 * s, (kt / 3) & 1);     // all warps consumed slot s
            issue(kt + 3);
        }
    }
    __syncthreads();   // all warps out of the mainloop before smem reuse

    // ---- epilogue: transpose through smem, fused BN + SiLU, coalesced STG ----
    float* eP = reinterpret_cast<float*>(smem + SM_OFF);   // [n 128][m 128], stride 132
#pragma unroll
    for (int i = 0; i < 4; i++) {
        int m = wm * 64 + i * 16 + rq;
#pragma unroll
        for (int j = 0; j < 4; j++) {
            int n = wn * 32 + j * 8 + 2 * qq;
            eP[n * 132 + m]           = acc[i][j][0];
            eP[(n + 1) * 132 + m]     = acc[i][j][1];
            eP[n * 132 + m + 8]       = acc[i][j][2];
            eP[(n + 1) * 132 + m + 8] = acc[i][j][3];
        }
    }
    __syncthreads();

#pragma unroll 1
    for (int idx = tid; idx < 128 * 32; idx += 256) {
        int row = idx >> 5;            // local output channel (uniform per warp)
        int seg = idx & 31;            // 4-float segment along m
        float4 v = *reinterpret_cast<const float4*>(eP + row * 132 + seg * 4);
        int oc = n0 + row;
        float s = g_bns[oc], t = g_bnb[oc];
        float z0 = v.x * s + t, z1 = v.y * s + t, z2 = v.z * s + t, z3 = v.w * s + t;
        float4 o4;
        o4.x = z0 / (1.0f + __expf(-z0));
        o4.y = z1 / (1.0f + __expf(-z1));
        o4.z = z2 / (1.0f + __expf(-z2));
        o4.w = z3 / (1.0f + __expf(-z3));
        *reinterpret_cast<float4*>(out + (((size_t)(b * 512 + oc)) << 12) + m0 + seg * 4) = o4;
    }
}

// ----------------------------------------------------------------------------
// Launch (3 kernels per call; g_sum starts zeroed: zero-init + k_mlp tail)
// ----------------------------------------------------------------------------
extern "C" void kernel_launch(void* const* d_in, const int* in_sizes, int n_in,
                              void* d_out, int out_size) {
    const float* x      = (const float*)d_in[0];
    const float* w1     = (const float*)d_in[1];
    const float* w2     = (const float*)d_in[2];
    const float* conv_w = (const float*)d_in[3];
    const float* gamma  = (const float*)d_in[4];
    const float* beta   = (const float*)d_in[5];
    const float* mean   = (const float*)d_in[6];
    const float* var    = (const float*)d_in[7];
    float* out = (float*)d_out;
    (void)in_sizes; (void)n_in; (void)out_size;

    cudaFuncSetAttribute(k_gemm, cudaFuncAttributeMaxDynamicSharedMemorySize, SMEM_SZ);

    k_wavelet<<<dim3(128, 8, 9), 256>>>(x, conv_w);
    k_mlp<<<9, 256>>>(w1, w2, gamma, beta, mean, var);
    k_gemm<<<dim3(4, 32, 8), 256, SMEM_SZ>>>(out);
}